// round 1
// baseline (speedup 1.0000x reference)
#include <cuda_runtime.h>
#include <cuda_bf16.h>
#include <math.h>

#define B_ 8
#define E_ 16384
#define O_ 256

// ---------------- scratch (__device__ globals; no allocs allowed) ----------------
__device__ float g_U [(size_t)B_*E_*128];   // from_up, edge-major
__device__ float g_X [(size_t)B_*E_*512];   // concat(conv1, from_down), edge-major
__device__ float g_Z [(size_t)B_*E_*256];   // conv output (pre-norm)
__device__ float g_X1[(size_t)B_*E_*256];
__device__ float g_X2[(size_t)B_*E_*256];
__device__ float g_Wup [5*128*256];
__device__ float g_W1r [5*512*256];
__device__ float g_W2ar[5*256*256];
__device__ float g_W2br[5*256*256];
__device__ float g_sum [B_*256];
__device__ float g_ssq [B_*256];
__device__ float g_mean[B_*256];
__device__ float g_rstd[B_*256];

// ---------------- weight reorder: W[o,c,kk] -> Wr[kk,c,o] ----------------
__global__ void prep_w(const float* __restrict__ W, float* __restrict__ Wr, int C)
{
    int i = blockIdx.x * blockDim.x + threadIdx.x;
    int total = 5 * C * 256;
    if (i < total) {
        int o  = i & 255;
        int t  = i >> 8;
        int c  = t % C;
        int kk = t / C;
        Wr[i] = W[(o * C + c) * 5 + kk];
    }
}

// ---------------- transpose [B,C,E] -> [B,E,os] (cols coff..coff+C) ----------------
__global__ void trans_ce_ec(const float* __restrict__ in, float* __restrict__ out,
                            int C, int os, int coff)
{
    __shared__ float tile[32][33];
    int b  = blockIdx.z;
    int e0 = blockIdx.x * 32, c0 = blockIdx.y * 32;
    const float* ip = in + ((size_t)b * C + c0) * E_ + e0;
    #pragma unroll
    for (int i = threadIdx.y; i < 32; i += 8)
        tile[i][threadIdx.x] = ip[(size_t)i * E_ + threadIdx.x];
    __syncthreads();
    float* op = out + ((size_t)(b * E_ + e0)) * os + coff + c0;
    #pragma unroll
    for (int i = threadIdx.y; i < 32; i += 8)
        op[(size_t)i * os + threadIdx.x] = tile[threadIdx.x][i];
}

// ---------------- transpose [B,E,256] -> [B,256,E] ----------------
__global__ void trans_ec_ce(const float* __restrict__ in, float* __restrict__ out)
{
    __shared__ float tile[32][33];
    int b  = blockIdx.z;
    int e0 = blockIdx.x * 32, c0 = blockIdx.y * 32;
    const float* ip = in + ((size_t)(b * E_ + e0)) * 256 + c0;
    #pragma unroll
    for (int i = threadIdx.y; i < 32; i += 8)
        tile[i][threadIdx.x] = ip[(size_t)i * 256 + threadIdx.x];
    __syncthreads();
    float* op = out + ((size_t)(b * 256 + c0)) * E_ + e0;
    #pragma unroll
    for (int i = threadIdx.y; i < 32; i += 8)
        op[(size_t)i * E_ + threadIdx.x] = tile[threadIdx.x][i];
}

// ---------------- fused gather + GEMM ----------------
// Xin: [B,E,C] edge-major. Wr: [5,C,256]. Yout: [B,E,ys] (writes cols 0..255).
// Tile: 128 edges x 128 outs, 256 threads, 8x8 per thread.
// K consumed in slabs of 80 = 5 feature kinds x 16 channels.
#define KSLAB 80
#define FS_LD 132   // padded row stride for Fs (k-major [80][132])

__global__ __launch_bounds__(256, 2)
void gconv(const float* __restrict__ Xin, int C,
           const int* __restrict__ ei,
           const float* __restrict__ Wr,
           const float* __restrict__ bias,
           float* __restrict__ Yout, int ys)
{
    extern __shared__ float sm[];
    float* Fs  = sm;                       // [80][132]
    float* Ws  = sm + KSLAB * FS_LD;       // [80][128]
    int*   snb = (int*)(Ws + KSLAB * 128); // [128*4] neighbor row bases (element offsets)

    const int b   = blockIdx.z;
    const int e0  = blockIdx.x * 128;
    const int o0  = blockIdx.y * 128;
    const int tid = threadIdx.x;

    {
        const int* eip = ei + ((size_t)(b * E_) + e0) * 4;
        for (int i = tid; i < 512; i += 256)
            snb[i] = (b * E_ + eip[i]) * C;
    }
    __syncthreads();

    float acc[8][8];
    #pragma unroll
    for (int i = 0; i < 8; i++)
        #pragma unroll
        for (int j = 0; j < 8; j++) acc[i][j] = 0.f;

    const int ex  = tid & 15;   // edge-group in GEMM
    const int oy  = tid >> 4;   // out-group in GEMM
    const int ccL = tid & 15;   // channel lane in gather
    const int eL0 = tid >> 4;   // edge base in gather
    const int cbase0 = (b * E_ + e0) * C;

    for (int c0 = 0; c0 < C; c0 += 16) {
        __syncthreads();
        // ---- load weight slab Ws[kk*16+cc][o] = Wr[kk][c0+cc][o0+o] ----
        #pragma unroll 1
        for (int i = tid; i < (KSLAB * 128 / 4); i += 256) {
            int row = i >> 5;
            int col = (i & 31) << 2;
            int kk  = row >> 4, cc = row & 15;
            *(float4*)&Ws[row * 128 + col] =
                *(const float4*)&Wr[(kk * C + c0 + cc) * 256 + o0 + col];
        }
        // ---- gather feature slab ----
        #pragma unroll 1
        for (int r = 0; r < 8; r++) {
            int eL = eL0 + r * 16;
            int c  = c0 + ccL;
            float x0 = Xin[cbase0 + eL * C + c];
            const int* nb = &snb[eL * 4];
            float x1 = Xin[nb[0] + c];
            float x2 = Xin[nb[1] + c];
            float x3 = Xin[nb[2] + c];
            float x4 = Xin[nb[3] + c];
            Fs[(ccL     ) * FS_LD + eL] = x0;
            Fs[(16 + ccL) * FS_LD + eL] = x1 + x3;
            Fs[(32 + ccL) * FS_LD + eL] = x2 + x4;
            Fs[(48 + ccL) * FS_LD + eL] = fabsf(x1 - x3);
            Fs[(64 + ccL) * FS_LD + eL] = fabsf(x2 - x4);
        }
        __syncthreads();
        // ---- 128x128x80 GEMM step ----
        #pragma unroll 8
        for (int k = 0; k < KSLAB; k++) {
            float4 a0  = *(const float4*)&Fs[k * FS_LD + ex * 4];
            float4 a1  = *(const float4*)&Fs[k * FS_LD + 64 + ex * 4];
            float4 b0v = *(const float4*)&Ws[k * 128 + oy * 4];
            float4 b1v = *(const float4*)&Ws[k * 128 + 64 + oy * 4];
            float A[8]  = {a0.x, a0.y, a0.z, a0.w, a1.x, a1.y, a1.z, a1.w};
            float Bv[8] = {b0v.x, b0v.y, b0v.z, b0v.w, b1v.x, b1v.y, b1v.z, b1v.w};
            #pragma unroll
            for (int i = 0; i < 8; i++)
                #pragma unroll
                for (int j = 0; j < 8; j++)
                    acc[i][j] = fmaf(A[i], Bv[j], acc[i][j]);
        }
    }

    // ---- epilogue: +bias, write [B,E,ys] ----
    float bv[8];
    #pragma unroll
    for (int j = 0; j < 4; j++) {
        bv[j]     = bias[o0 + oy * 4 + j];
        bv[4 + j] = bias[o0 + 64 + oy * 4 + j];
    }
    #pragma unroll
    for (int i = 0; i < 8; i++) {
        int er = (i < 4) ? (ex * 4 + i) : (64 + ex * 4 + (i - 4));
        size_t base = ((size_t)(b * E_ + e0 + er)) * ys;
        float4 v0 = make_float4(acc[i][0] + bv[0], acc[i][1] + bv[1],
                                acc[i][2] + bv[2], acc[i][3] + bv[3]);
        float4 v1 = make_float4(acc[i][4] + bv[4], acc[i][5] + bv[5],
                                acc[i][6] + bv[6], acc[i][7] + bv[7]);
        *(float4*)&Yout[base + o0 + oy * 4] = v0;
        *(float4*)&Yout[base + o0 + 64 + oy * 4] = v1;
    }
}

// ---------------- instance norm over E per (b,c) ----------------
__global__ void reduce_stats(const float* __restrict__ Z,
                             float* __restrict__ gsum, float* __restrict__ gssq)
{
    int b  = blockIdx.x >> 6;
    int ch = blockIdx.x & 63;
    int c  = threadIdx.x;
    const float* p = Z + ((size_t)(b * E_) + ch * 256) * 256 + c;
    float s = 0.f, q = 0.f;
    #pragma unroll 4
    for (int e = 0; e < 256; e++) {
        float v = p[(size_t)e * 256];
        s += v;
        q = fmaf(v, v, q);
    }
    atomicAdd(&gsum[b * 256 + c], s);
    atomicAdd(&gssq[b * 256 + c], q);
}

__global__ void finalize_stats(const float* __restrict__ gsum, const float* __restrict__ gssq,
                               float* __restrict__ mean, float* __restrict__ rstd)
{
    int i = blockIdx.x * blockDim.x + threadIdx.x;
    if (i < B_ * 256) {
        float m = gsum[i] * (1.f / E_);
        float v = gssq[i] * (1.f / E_) - m * m;
        mean[i] = m;
        rstd[i] = rsqrtf(v + 1e-5f);
    }
}

// out = relu((Z-mean)*rstd [+ res])
__global__ void apply_norm(const float* __restrict__ Z, const float* __restrict__ res,
                           const float* __restrict__ mean, const float* __restrict__ rstd,
                           float* __restrict__ out, int addres)
{
    size_t i = (size_t)blockIdx.x * blockDim.x + threadIdx.x;   // float4 index
    int b = (int)(i >> 20);          // E_*256/4 = 2^20 float4 per batch
    int c = ((int)i & 63) * 4;
    float4 z = ((const float4*)Z)[i];
    int mi = b * 256 + c;
    float m0 = mean[mi], m1 = mean[mi + 1], m2 = mean[mi + 2], m3 = mean[mi + 3];
    float r0 = rstd[mi], r1 = rstd[mi + 1], r2 = rstd[mi + 2], r3 = rstd[mi + 3];
    float4 o;
    o.x = (z.x - m0) * r0;
    o.y = (z.y - m1) * r1;
    o.z = (z.z - m2) * r2;
    o.w = (z.w - m3) * r3;
    if (addres) {
        float4 rv = ((const float4*)res)[i];
        o.x += rv.x; o.y += rv.y; o.z += rv.z; o.w += rv.w;
    }
    o.x = fmaxf(o.x, 0.f);
    o.y = fmaxf(o.y, 0.f);
    o.z = fmaxf(o.z, 0.f);
    o.w = fmaxf(o.w, 0.f);
    ((float4*)out)[i] = o;
}

// ---------------- host ----------------
extern "C" void kernel_launch(void* const* d_in, const int* in_sizes, int n_in,
                              void* d_out, int out_size)
{
    const float* from_up   = (const float*)d_in[0];
    const float* from_down = (const float*)d_in[1];
    const int*   ei        = (const int*)  d_in[2];
    const float* W_up = (const float*)d_in[3];
    const float* b_up = (const float*)d_in[4];
    const float* W1   = (const float*)d_in[5];
    const float* b1   = (const float*)d_in[6];
    const float* W2a  = (const float*)d_in[7];
    const float* b2a  = (const float*)d_in[8];
    const float* W2b  = (const float*)d_in[9];
    const float* b2b  = (const float*)d_in[10];
    float* out = (float*)d_out;

    float *U, *X, *Z, *X1, *X2, *Wup, *W1r, *W2ar, *W2br, *sum_, *ssq_, *mean_, *rstd_;
    cudaGetSymbolAddress((void**)&U,    g_U);
    cudaGetSymbolAddress((void**)&X,    g_X);
    cudaGetSymbolAddress((void**)&Z,    g_Z);
    cudaGetSymbolAddress((void**)&X1,   g_X1);
    cudaGetSymbolAddress((void**)&X2,   g_X2);
    cudaGetSymbolAddress((void**)&Wup,  g_Wup);
    cudaGetSymbolAddress((void**)&W1r,  g_W1r);
    cudaGetSymbolAddress((void**)&W2ar, g_W2ar);
    cudaGetSymbolAddress((void**)&W2br, g_W2br);
    cudaGetSymbolAddress((void**)&sum_,  g_sum);
    cudaGetSymbolAddress((void**)&ssq_,  g_ssq);
    cudaGetSymbolAddress((void**)&mean_, g_mean);
    cudaGetSymbolAddress((void**)&rstd_, g_rstd);

    const int SMEM = (KSLAB * FS_LD + KSLAB * 128) * 4 + 512 * 4;  // 85248
    cudaFuncSetAttribute(gconv, cudaFuncAttributeMaxDynamicSharedMemorySize, SMEM);

    // weight reorders
    prep_w<<<(5 * 128 * 256 + 255) / 256, 256>>>(W_up, Wup, 128);
    prep_w<<<(5 * 512 * 256 + 255) / 256, 256>>>(W1,   W1r, 512);
    prep_w<<<(5 * 256 * 256 + 255) / 256, 256>>>(W2a,  W2ar, 256);
    prep_w<<<(5 * 256 * 256 + 255) / 256, 256>>>(W2b,  W2br, 256);

    dim3 tb(32, 8);
    trans_ce_ec<<<dim3(E_ / 32, 128 / 32, B_), tb>>>(from_up,   U, 128, 128, 0);
    trans_ce_ec<<<dim3(E_ / 32, 256 / 32, B_), tb>>>(from_down, X, 256, 512, 256);

    dim3 cg(E_ / 128, 2, B_);
    // conv1: writes concat cols 0..255 of X
    gconv<<<cg, 256, SMEM>>>(U, 128, ei, Wup, b_up, X, 512);
    // conv2 over concat
    gconv<<<cg, 256, SMEM>>>(X, 512, ei, W1r, b1, Z, 256);

    // norm1 -> X1
    cudaMemsetAsync(sum_, 0, B_ * 256 * 4);
    cudaMemsetAsync(ssq_, 0, B_ * 256 * 4);
    reduce_stats<<<B_ * 64, 256>>>(Z, sum_, ssq_);
    finalize_stats<<<(B_ * 256 + 255) / 256, 256>>>(sum_, ssq_, mean_, rstd_);
    apply_norm<<<32768, 256>>>(Z, Z, mean_, rstd_, X1, 0);

    // residual block A: X2 = relu(norm(conv(X1)) + X1)
    gconv<<<cg, 256, SMEM>>>(X1, 256, ei, W2ar, b2a, Z, 256);
    cudaMemsetAsync(sum_, 0, B_ * 256 * 4);
    cudaMemsetAsync(ssq_, 0, B_ * 256 * 4);
    reduce_stats<<<B_ * 64, 256>>>(Z, sum_, ssq_);
    finalize_stats<<<(B_ * 256 + 255) / 256, 256>>>(sum_, ssq_, mean_, rstd_);
    apply_norm<<<32768, 256>>>(Z, X1, mean_, rstd_, X2, 1);

    // residual block B: result = relu(norm(conv(X2)) + X2) -> X1
    gconv<<<cg, 256, SMEM>>>(X2, 256, ei, W2br, b2b, Z, 256);
    cudaMemsetAsync(sum_, 0, B_ * 256 * 4);
    cudaMemsetAsync(ssq_, 0, B_ * 256 * 4);
    reduce_stats<<<B_ * 64, 256>>>(Z, sum_, ssq_);
    finalize_stats<<<(B_ * 256 + 255) / 256, 256>>>(sum_, ssq_, mean_, rstd_);
    apply_norm<<<32768, 256>>>(Z, X2, mean_, rstd_, X1, 1);

    // final layout [B,256,E]
    trans_ec_ce<<<dim3(E_ / 32, 256 / 32, B_), tb>>>(X1, out);
}

// round 3
// speedup vs baseline: 2.3174x; 2.3174x over previous
#include <cuda_runtime.h>
#include <cuda_bf16.h>
#include <math.h>
#include <stdint.h>

#define B_ 8
#define E_ 16384
#define O_ 256

// ---------------- scratch (__device__ globals; no allocs allowed) ----------------
__device__ float g_U [(size_t)B_*E_*128];   // from_up, edge-major
__device__ float g_X [(size_t)B_*E_*512];   // concat(conv1, from_down), edge-major
__device__ float g_Z [(size_t)B_*E_*256];   // conv output (pre-norm)
__device__ float g_X1[(size_t)B_*E_*256];
__device__ float g_X2[(size_t)B_*E_*256];
__device__ float g_Wup [5*128*256];
__device__ float g_W1r [5*512*256];
__device__ float g_W2ar[5*256*256];
__device__ float g_W2br[5*256*256];
__device__ float g_sum [B_*256];
__device__ float g_ssq [B_*256];
__device__ float g_mean[B_*256];
__device__ float g_rstd[B_*256];

__device__ __constant__ int c_ORD[5] = {0, 1, 3, 2, 4};

__device__ __forceinline__ float to_tf32(float x) {
    float r;
    asm("cvt.rna.tf32.f32 %0, %1;" : "=f"(r) : "f"(x));
    return r;
}

__device__ __forceinline__ void mma1688(float* d,
                                        uint32_t a0, uint32_t a1, uint32_t a2, uint32_t a3,
                                        uint32_t b0, uint32_t b1)
{
    asm volatile(
        "mma.sync.aligned.m16n8k8.row.col.f32.tf32.tf32.f32 "
        "{%0,%1,%2,%3}, {%4,%5,%6,%7}, {%8,%9}, {%0,%1,%2,%3};"
        : "+f"(d[0]), "+f"(d[1]), "+f"(d[2]), "+f"(d[3])
        : "r"(a0), "r"(a1), "r"(a2), "r"(a3), "r"(b0), "r"(b1));
}

// ---------------- weight image prep: W[o,c,kk] -> [slab][o 0..255][k16], tf32 ----------------
// slab s: kind = ORD[s%5], channels [(s/5)*16, +16)
__global__ void prep_w_img(const float* __restrict__ W, float* __restrict__ Wimg, int C)
{
    int i = blockIdx.x * blockDim.x + threadIdx.x;
    int total = 5 * C * 256;
    if (i >= total) return;
    int slab   = i >> 12;
    int within = i & 4095;
    int o  = within >> 4;
    int kk = within & 15;
    int chunk = slab / 5;
    int kind  = c_ORD[slab % 5];
    int c = chunk * 16 + kk;
    Wimg[i] = to_tf32(W[(o * C + c) * 5 + kind]);
}

// ---------------- transpose [B,C,E] -> [B,E,os] ----------------
__global__ void trans_ce_ec(const float* __restrict__ in, float* __restrict__ out,
                            int C, int os, int coff)
{
    __shared__ float tile[32][33];
    int b  = blockIdx.z;
    int e0 = blockIdx.x * 32, c0 = blockIdx.y * 32;
    const float* ip = in + ((size_t)b * C + c0) * E_ + e0;
    #pragma unroll
    for (int i = threadIdx.y; i < 32; i += 8)
        tile[i][threadIdx.x] = ip[(size_t)i * E_ + threadIdx.x];
    __syncthreads();
    float* op = out + ((size_t)(b * E_ + e0)) * os + coff + c0;
    #pragma unroll
    for (int i = threadIdx.y; i < 32; i += 8)
        op[(size_t)i * os + threadIdx.x] = tile[threadIdx.x][i];
}

// ---------------- transpose [B,E,256] -> [B,256,E] ----------------
__global__ void trans_ec_ce(const float* __restrict__ in, float* __restrict__ out)
{
    __shared__ float tile[32][33];
    int b  = blockIdx.z;
    int e0 = blockIdx.x * 32, c0 = blockIdx.y * 32;
    const float* ip = in + ((size_t)(b * E_ + e0)) * 256 + c0;
    #pragma unroll
    for (int i = threadIdx.y; i < 32; i += 8)
        tile[i][threadIdx.x] = ip[(size_t)i * 256 + threadIdx.x];
    __syncthreads();
    float* op = out + ((size_t)(b * 256 + c0)) * E_ + e0;
    #pragma unroll
    for (int i = threadIdx.y; i < 32; i += 8)
        op[(size_t)i * E_ + threadIdx.x] = tile[threadIdx.x][i];
}

// ---------------- fused gather + tensor-core GEMM (mma.sync tf32) ----------------
// Block: 128 edges x 128 outs. 8 warps in 2(M) x 4(N): warp tile 64 x 32.
// K in slabs of 16 (one feature kind x 16 channels). Double-buffered smem,
// register-staged global loads, one __syncthreads per slab.
#define ALD 20   // padded row stride (floats): conflict-free fragment LDS

__global__ __launch_bounds__(256, 2)
void gconv_mma(const float* __restrict__ Xin, int C,
               const int* __restrict__ ei,
               const float* __restrict__ Wimg,
               const float* __restrict__ bias,
               float* __restrict__ Yout, int ys)
{
    __shared__ float As[2][128 * ALD];
    __shared__ float Bs[2][128 * ALD];
    __shared__ int   snb[512];

    const int tid = threadIdx.x;
    const int wid = tid >> 5;
    const int lane = tid & 31;
    const int g = lane >> 2;     // fragment group (row)
    const int t = lane & 3;      // thread-in-group (col)
    const int wm = wid >> 2;     // 0/1 : edge-half
    const int wn = wid & 3;      // 0..3: out-quarter
    const int b  = blockIdx.z;
    const int e0 = blockIdx.x * 128;
    const int o0 = blockIdx.y * 128;

    {
        const int* eip = ei + ((size_t)(b * E_) + e0) * 4;
        for (int i = tid; i < 512; i += 256)
            snb[i] = (b * E_ + eip[i]) * C;
    }
    __syncthreads();

    const int x0base = (b * E_ + e0) * C;
    const int slabs  = 5 * (C / 16);

    float acc[4][4][4];
    #pragma unroll
    for (int mt = 0; mt < 4; mt++)
        #pragma unroll
        for (int nt = 0; nt < 4; nt++)
            #pragma unroll
            for (int r = 0; r < 4; r++) acc[mt][nt][r] = 0.f;

    float4 ra[2], rb[2];

    // ---- slab loader into registers ----
    auto load_slab = [&](int s) {
        const int kind = c_ORD[s % 5];
        const int cb   = (s / 5) * 16;
        #pragma unroll
        for (int j = 0; j < 2; j++) {
            int v = tid + j * 256;
            int edge = v >> 2;
            int c    = cb + (v & 3) * 4;
            if (kind == 0) {
                ra[j] = *(const float4*)&Xin[x0base + edge * C + c];
            } else {
                int na = (kind == 1 || kind == 3) ? 0 : 1;
                float4 p = *(const float4*)&Xin[snb[edge * 4 + na] + c];
                float4 q = *(const float4*)&Xin[snb[edge * 4 + na + 2] + c];
                if (kind <= 2)
                    ra[j] = make_float4(p.x + q.x, p.y + q.y, p.z + q.z, p.w + q.w);
                else
                    ra[j] = make_float4(fabsf(p.x - q.x), fabsf(p.y - q.y),
                                        fabsf(p.z - q.z), fabsf(p.w - q.w));
            }
            rb[j] = *(const float4*)&Wimg[(((size_t)s * 256) + o0 + edge) * 16 + (v & 3) * 4];
        }
    };
    auto store_slab = [&](int buf) {
        #pragma unroll
        for (int j = 0; j < 2; j++) {
            int v = tid + j * 256;
            int row = v >> 2;
            int c4  = (v & 3) * 4;
            float4 a = ra[j], w = rb[j];
            a.x = to_tf32(a.x); a.y = to_tf32(a.y);
            a.z = to_tf32(a.z); a.w = to_tf32(a.w);
            *(float4*)&As[buf][row * ALD + c4] = a;
            *(float4*)&Bs[buf][row * ALD + c4] = w;
        }
    };

    load_slab(0);
    store_slab(0);
    __syncthreads();

    for (int s = 0; s < slabs; s++) {
        int cur = s & 1;
        if (s + 1 < slabs) load_slab(s + 1);   // LDG latency overlaps MMA below

        const float* A = As[cur];
        const float* Bt = Bs[cur];
        #pragma unroll
        for (int ks = 0; ks < 2; ks++) {
            int kb = ks * 8;
            uint32_t af[4][4], bf[4][2];
            #pragma unroll
            for (int mt = 0; mt < 4; mt++) {
                int r0 = wm * 64 + mt * 16 + g;
                af[mt][0] = __float_as_uint(A[r0 * ALD + kb + t]);
                af[mt][1] = __float_as_uint(A[(r0 + 8) * ALD + kb + t]);
                af[mt][2] = __float_as_uint(A[r0 * ALD + kb + 4 + t]);
                af[mt][3] = __float_as_uint(A[(r0 + 8) * ALD + kb + 4 + t]);
            }
            #pragma unroll
            for (int nt = 0; nt < 4; nt++) {
                int nc = wn * 32 + nt * 8 + g;
                bf[nt][0] = __float_as_uint(Bt[nc * ALD + kb + t]);
                bf[nt][1] = __float_as_uint(Bt[nc * ALD + kb + 4 + t]);
            }
            #pragma unroll
            for (int mt = 0; mt < 4; mt++)
                #pragma unroll
                for (int nt = 0; nt < 4; nt++)
                    mma1688(acc[mt][nt], af[mt][0], af[mt][1], af[mt][2], af[mt][3],
                            bf[nt][0], bf[nt][1]);
        }

        if (s + 1 < slabs) store_slab(cur ^ 1);
        __syncthreads();
    }

    // ---- epilogue: +bias, float2 stores ----
    #pragma unroll
    for (int nt = 0; nt < 4; nt++) {
        int col = o0 + wn * 32 + nt * 8 + 2 * t;
        float bv0 = bias[col], bv1 = bias[col + 1];
        #pragma unroll
        for (int mt = 0; mt < 4; mt++) {
            int row = e0 + wm * 64 + mt * 16 + g;
            float2 v0 = make_float2(acc[mt][nt][0] + bv0, acc[mt][nt][1] + bv1);
            float2 v1 = make_float2(acc[mt][nt][2] + bv0, acc[mt][nt][3] + bv1);
            *(float2*)&Yout[((size_t)(b * E_ + row)) * ys + col] = v0;
            *(float2*)&Yout[((size_t)(b * E_ + row + 8)) * ys + col] = v1;
        }
    }
}

// ---------------- instance norm over E per (b,c) ----------------
__global__ void reduce_stats(const float* __restrict__ Z,
                             float* __restrict__ gsum, float* __restrict__ gssq)
{
    int b  = blockIdx.x >> 6;
    int ch = blockIdx.x & 63;
    int c  = threadIdx.x;
    const float* p = Z + ((size_t)(b * E_) + ch * 256) * 256 + c;
    float s = 0.f, q = 0.f;
    #pragma unroll 4
    for (int e = 0; e < 256; e++) {
        float v = p[(size_t)e * 256];
        s += v;
        q = fmaf(v, v, q);
    }
    atomicAdd(&gsum[b * 256 + c], s);
    atomicAdd(&gssq[b * 256 + c], q);
}

__global__ void finalize_stats(const float* __restrict__ gsum, const float* __restrict__ gssq,
                               float* __restrict__ mean, float* __restrict__ rstd)
{
    int i = blockIdx.x * blockDim.x + threadIdx.x;
    if (i < B_ * 256) {
        float m = gsum[i] * (1.f / E_);
        float v = gssq[i] * (1.f / E_) - m * m;
        mean[i] = m;
        rstd[i] = rsqrtf(v + 1e-5f);
    }
}

__global__ void apply_norm(const float* __restrict__ Z, const float* __restrict__ res,
                           const float* __restrict__ mean, const float* __restrict__ rstd,
                           float* __restrict__ out, int addres)
{
    size_t i = (size_t)blockIdx.x * blockDim.x + threadIdx.x;
    int b = (int)(i >> 20);
    int c = ((int)i & 63) * 4;
    float4 z = ((const float4*)Z)[i];
    int mi = b * 256 + c;
    float m0 = mean[mi], m1 = mean[mi + 1], m2 = mean[mi + 2], m3 = mean[mi + 3];
    float r0 = rstd[mi], r1 = rstd[mi + 1], r2 = rstd[mi + 2], r3 = rstd[mi + 3];
    float4 o;
    o.x = (z.x - m0) * r0;
    o.y = (z.y - m1) * r1;
    o.z = (z.z - m2) * r2;
    o.w = (z.w - m3) * r3;
    if (addres) {
        float4 rv = ((const float4*)res)[i];
        o.x += rv.x; o.y += rv.y; o.z += rv.z; o.w += rv.w;
    }
    o.x = fmaxf(o.x, 0.f);
    o.y = fmaxf(o.y, 0.f);
    o.z = fmaxf(o.z, 0.f);
    o.w = fmaxf(o.w, 0.f);
    ((float4*)out)[i] = o;
}

// ---------------- host ----------------
extern "C" void kernel_launch(void* const* d_in, const int* in_sizes, int n_in,
                              void* d_out, int out_size)
{
    const float* from_up   = (const float*)d_in[0];
    const float* from_down = (const float*)d_in[1];
    const int*   ei        = (const int*)  d_in[2];
    const float* W_up = (const float*)d_in[3];
    const float* b_up = (const float*)d_in[4];
    const float* W1   = (const float*)d_in[5];
    const float* b1   = (const float*)d_in[6];
    const float* W2a  = (const float*)d_in[7];
    const float* b2a  = (const float*)d_in[8];
    const float* W2b  = (const float*)d_in[9];
    const float* b2b  = (const float*)d_in[10];
    float* out = (float*)d_out;

    float *U, *X, *Z, *X1, *X2, *Wup, *W1r, *W2ar, *W2br, *sum_, *ssq_, *mean_, *rstd_;
    cudaGetSymbolAddress((void**)&U,    g_U);
    cudaGetSymbolAddress((void**)&X,    g_X);
    cudaGetSymbolAddress((void**)&Z,    g_Z);
    cudaGetSymbolAddress((void**)&X1,   g_X1);
    cudaGetSymbolAddress((void**)&X2,   g_X2);
    cudaGetSymbolAddress((void**)&Wup,  g_Wup);
    cudaGetSymbolAddress((void**)&W1r,  g_W1r);
    cudaGetSymbolAddress((void**)&W2ar, g_W2ar);
    cudaGetSymbolAddress((void**)&W2br, g_W2br);
    cudaGetSymbolAddress((void**)&sum_,  g_sum);
    cudaGetSymbolAddress((void**)&ssq_,  g_ssq);
    cudaGetSymbolAddress((void**)&mean_, g_mean);
    cudaGetSymbolAddress((void**)&rstd_, g_rstd);

    // weight images (slab-ordered [slab][o][k16], tf32-rounded)
    prep_w_img<<<(5 * 128 * 256 + 255) / 256, 256>>>(W_up, Wup, 128);
    prep_w_img<<<(5 * 512 * 256 + 255) / 256, 256>>>(W1,   W1r, 512);
    prep_w_img<<<(5 * 256 * 256 + 255) / 256, 256>>>(W2a,  W2ar, 256);
    prep_w_img<<<(5 * 256 * 256 + 255) / 256, 256>>>(W2b,  W2br, 256);

    dim3 tb(32, 8);
    trans_ce_ec<<<dim3(E_ / 32, 128 / 32, B_), tb>>>(from_up,   U, 128, 128, 0);
    trans_ce_ec<<<dim3(E_ / 32, 256 / 32, B_), tb>>>(from_down, X, 256, 512, 256);

    dim3 cg(E_ / 128, 2, B_);
    // conv1: writes concat cols 0..255 of X
    gconv_mma<<<cg, 256>>>(U, 128, ei, Wup, b_up, X, 512);
    // conv2 over concat
    gconv_mma<<<cg, 256>>>(X, 512, ei, W1r, b1, Z, 256);

    // norm1 -> X1
    cudaMemsetAsync(sum_, 0, B_ * 256 * 4);
    cudaMemsetAsync(ssq_, 0, B_ * 256 * 4);
    reduce_stats<<<B_ * 64, 256>>>(Z, sum_, ssq_);
    finalize_stats<<<(B_ * 256 + 255) / 256, 256>>>(sum_, ssq_, mean_, rstd_);
    apply_norm<<<32768, 256>>>(Z, Z, mean_, rstd_, X1, 0);

    // residual block A
    gconv_mma<<<cg, 256>>>(X1, 256, ei, W2ar, b2a, Z, 256);
    cudaMemsetAsync(sum_, 0, B_ * 256 * 4);
    cudaMemsetAsync(ssq_, 0, B_ * 256 * 4);
    reduce_stats<<<B_ * 64, 256>>>(Z, sum_, ssq_);
    finalize_stats<<<(B_ * 256 + 255) / 256, 256>>>(sum_, ssq_, mean_, rstd_);
    apply_norm<<<32768, 256>>>(Z, X1, mean_, rstd_, X2, 1);

    // residual block B
    gconv_mma<<<cg, 256>>>(X2, 256, ei, W2br, b2b, Z, 256);
    cudaMemsetAsync(sum_, 0, B_ * 256 * 4);
    cudaMemsetAsync(ssq_, 0, B_ * 256 * 4);
    reduce_stats<<<B_ * 64, 256>>>(Z, sum_, ssq_);
    finalize_stats<<<(B_ * 256 + 255) / 256, 256>>>(sum_, ssq_, mean_, rstd_);
    apply_norm<<<32768, 256>>>(Z, X2, mean_, rstd_, X1, 1);

    // final layout [B,256,E]
    trans_ec_ce<<<dim3(E_ / 32, 256 / 32, B_), tb>>>(X1, out);
}

// round 4
// speedup vs baseline: 2.8059x; 1.2108x over previous
#include <cuda_runtime.h>
#include <cuda_bf16.h>
#include <math.h>
#include <stdint.h>

#define B_ 8
#define E_ 16384
#define O_ 256

// ---------------- scratch (__device__ globals; no allocs allowed) ----------------
__device__ float g_U [(size_t)B_*E_*128];   // from_up, edge-major
__device__ float g_X [(size_t)B_*E_*512];   // concat(conv1, from_down), edge-major
__device__ float g_Z [(size_t)B_*E_*256];   // conv output (pre-norm)
__device__ float g_X1[(size_t)B_*E_*256];
__device__ float g_X2[(size_t)B_*E_*256];
__device__ float g_Wup [5*128*256];
__device__ float g_W1r [5*512*256];
__device__ float g_W2ar[5*256*256];
__device__ float g_W2br[5*256*256];
__device__ float g_sum [B_*256];
__device__ float g_ssq [B_*256];
__device__ float g_mean[B_*256];
__device__ float g_rstd[B_*256];

__device__ __forceinline__ float to_tf32(float x) {
    float r;
    asm("cvt.rna.tf32.f32 %0, %1;" : "=f"(r) : "f"(x));
    return r;
}

__device__ __forceinline__ void mma1688(float* d,
                                        uint32_t a0, uint32_t a1, uint32_t a2, uint32_t a3,
                                        uint32_t b0, uint32_t b1)
{
    asm volatile(
        "mma.sync.aligned.m16n8k8.row.col.f32.tf32.tf32.f32 "
        "{%0,%1,%2,%3}, {%4,%5,%6,%7}, {%8,%9}, {%0,%1,%2,%3};"
        : "+f"(d[0]), "+f"(d[1]), "+f"(d[2]), "+f"(d[3])
        : "r"(a0), "r"(a1), "r"(a2), "r"(a3), "r"(b0), "r"(b1));
}

__device__ __forceinline__ uint32_t smem_u32(const void* p) {
    uint32_t a;
    asm("{ .reg .u64 t; cvta.to.shared.u64 t, %1; cvt.u32.u64 %0, t; }" : "=r"(a) : "l"(p));
    return a;
}
#define CP_ASYNC16(dst, src) \
    asm volatile("cp.async.cg.shared.global [%0], [%1], 16;" :: "r"(dst), "l"(src))
#define CP_COMMIT() asm volatile("cp.async.commit_group;" ::: "memory")
#define CP_WAIT1()  asm volatile("cp.async.wait_group 1;" ::: "memory")
#define CP_WAIT0()  asm volatile("cp.async.wait_group 0;" ::: "memory")

// ---------------- slab map ----------------
// slab s (32 K-rows): cc = s/5, r = s%5
//  r=0: kind0 (center), channels [32cc, 32cc+32)
//  r=1: pair(1,3) chunk [32cc, +16)      rows 0-15 = n1+n3, rows 16-31 = |n1-n3|
//  r=2: pair(1,3) chunk [32cc+16, +16)
//  r=3: pair(2,4) chunk [32cc, +16)      rows = n2+n4 ; |n2-n4|
//  r=4: pair(2,4) chunk [32cc+16, +16)

// ---------------- weight image prep: W[o,c,kk] -> [slab][o 0..255][k32], tf32 ----------------
__global__ void prep_w_img(const float* __restrict__ W, float* __restrict__ Wimg, int C)
{
    int i = blockIdx.x * blockDim.x + threadIdx.x;
    int total = 5 * (C / 32) * 8192;
    if (i >= total) return;
    int slab   = i >> 13;
    int within = i & 8191;
    int o = within >> 5;
    int k = within & 31;
    int cc = slab / 5, r = slab % 5;
    int kind, c;
    if (r == 0) {
        kind = 0; c = 32 * cc + k;
    } else {
        int base  = (r <= 2) ? 1 : 2;
        int pairc = 32 * cc + ((r == 2 || r == 4) ? 16 : 0);
        if (k < 16) { kind = base;     c = pairc + k; }
        else        { kind = base + 2; c = pairc + k - 16; }
    }
    Wimg[i] = to_tf32(W[(o * C + c) * 5 + kind]);
}

// ---------------- transpose [B,C,E] -> [B,E,os] ----------------
__global__ void trans_ce_ec(const float* __restrict__ in, float* __restrict__ out,
                            int C, int os, int coff)
{
    __shared__ float tile[32][33];
    int b  = blockIdx.z;
    int e0 = blockIdx.x * 32, c0 = blockIdx.y * 32;
    const float* ip = in + ((size_t)b * C + c0) * E_ + e0;
    #pragma unroll
    for (int i = threadIdx.y; i < 32; i += 8)
        tile[i][threadIdx.x] = ip[(size_t)i * E_ + threadIdx.x];
    __syncthreads();
    float* op = out + ((size_t)(b * E_ + e0)) * os + coff + c0;
    #pragma unroll
    for (int i = threadIdx.y; i < 32; i += 8)
        op[(size_t)i * os + threadIdx.x] = tile[threadIdx.x][i];
}

// ---------------- transpose [B,E,256] -> [B,256,E] ----------------
__global__ void trans_ec_ce(const float* __restrict__ in, float* __restrict__ out)
{
    __shared__ float tile[32][33];
    int b  = blockIdx.z;
    int e0 = blockIdx.x * 32, c0 = blockIdx.y * 32;
    const float* ip = in + ((size_t)(b * E_ + e0)) * 256 + c0;
    #pragma unroll
    for (int i = threadIdx.y; i < 32; i += 8)
        tile[i][threadIdx.x] = ip[(size_t)i * 256 + threadIdx.x];
    __syncthreads();
    float* op = out + ((size_t)(b * 256 + c0)) * E_ + e0;
    #pragma unroll
    for (int i = threadIdx.y; i < 32; i += 8)
        op[(size_t)i * E_ + threadIdx.x] = tile[threadIdx.x][i];
}

// ---------------- fused gather + tensor-core GEMM ----------------
// Block: 128 edges x 256 outs, 512 threads (16 warps, 4x4: warp tile 32x64).
// K in 32-row kind-paired slabs; cp.async for B; register-staged gathers for A.
#define ALD 36                       // padded row stride (floats)
#define A_FLOATS (128 * ALD)         // 4608
#define B_FLOATS (256 * ALD)         // 9216
#define SMEM_BYTES ((2 * A_FLOATS + 2 * B_FLOATS) * 4 + 512 * 4)   // 112640

__global__ __launch_bounds__(512, 1)
void gconv_mma(const float* __restrict__ Xin, int C,
               const int* __restrict__ ei,
               const float* __restrict__ Wimg,
               const float* __restrict__ bias,
               float* __restrict__ Yout, int ys)
{
    extern __shared__ float smf[];
    float* smA = smf;                       // 2 x 128 x 36
    float* smB = smf + 2 * A_FLOATS;        // 2 x 256 x 36
    int*   snb = (int*)(smf + 2 * A_FLOATS + 2 * B_FLOATS);
    const uint32_t sB_u32 = smem_u32(smB);

    const int tid  = threadIdx.x;
    const int wid  = tid >> 5;
    const int lane = tid & 31;
    const int g = lane >> 2;
    const int t = lane & 3;
    const int wm = wid >> 2;     // 0..3: 32-edge quarter
    const int wn = wid & 3;      // 0..3: 64-out quarter
    const int b  = blockIdx.z;
    const int e0 = blockIdx.x * 128;

    {
        const int* eip = ei + ((size_t)(b * E_) + e0) * 4;
        for (int i = tid; i < 512; i += 512)
            snb[i] = (b * E_ + eip[i]) * C;
        for (int i = tid + 512; i < 512; i += 512) {}
    }
    // (512 threads, 512 entries: one each)
    __syncthreads();

    const int x0base = (b * E_ + e0) * C;
    const int slabs  = 5 * (C / 32);

    float acc[2][8][4];
    #pragma unroll
    for (int mt = 0; mt < 2; mt++)
        #pragma unroll
        for (int nt = 0; nt < 8; nt++)
            #pragma unroll
            for (int rr = 0; rr < 4; rr++) acc[mt][nt][rr] = 0.f;

    float4 ga[2];

    auto gather = [&](int s) {
        int cc = s / 5, r = s % 5;
        if (r == 0) {
            #pragma unroll
            for (int j = 0; j < 2; j++) {
                int v = tid + j * 512;
                int edge = v >> 3, c4 = (v & 7) * 4;
                ga[j] = *(const float4*)&Xin[x0base + edge * C + 32 * cc + c4];
            }
        } else {
            int na = (r <= 2) ? 0 : 1;
            int pc = 32 * cc + ((r == 2 || r == 4) ? 16 : 0);
            int edge = tid >> 2, c4 = (tid & 3) * 4;
            int c = pc + c4;
            float4 p = *(const float4*)&Xin[snb[edge * 4 + na] + c];
            float4 q = *(const float4*)&Xin[snb[edge * 4 + na + 2] + c];
            ga[0] = make_float4(p.x + q.x, p.y + q.y, p.z + q.z, p.w + q.w);
            ga[1] = make_float4(fabsf(p.x - q.x), fabsf(p.y - q.y),
                                fabsf(p.z - q.z), fabsf(p.w - q.w));
        }
    };
    auto storeA = [&](int s, int buf) {
        float* A = smA + buf * A_FLOATS;
        int r = s % 5;
        if (r == 0) {
            #pragma unroll
            for (int j = 0; j < 2; j++) {
                int v = tid + j * 512;
                int edge = v >> 3, k = (v & 7) * 4;
                float4 a = ga[j];
                a.x = to_tf32(a.x); a.y = to_tf32(a.y);
                a.z = to_tf32(a.z); a.w = to_tf32(a.w);
                *(float4*)&A[edge * ALD + k] = a;
            }
        } else {
            int edge = tid >> 2, k = (tid & 3) * 4;
            float4 sv = ga[0], dv = ga[1];
            sv.x = to_tf32(sv.x); sv.y = to_tf32(sv.y);
            sv.z = to_tf32(sv.z); sv.w = to_tf32(sv.w);
            dv.x = to_tf32(dv.x); dv.y = to_tf32(dv.y);
            dv.z = to_tf32(dv.z); dv.w = to_tf32(dv.w);
            *(float4*)&A[edge * ALD + k]      = sv;
            *(float4*)&A[edge * ALD + 16 + k] = dv;
        }
    };
    auto copyB = [&](int s, int buf) {
        const float* src = Wimg + (size_t)s * 8192;
        uint32_t dstb = sB_u32 + buf * (B_FLOATS * 4);
        #pragma unroll
        for (int j = 0; j < 4; j++) {
            int idx = tid + j * 512;
            int o = idx >> 3, k4 = (idx & 7) * 4;
            CP_ASYNC16(dstb + (uint32_t)(o * ALD + k4) * 4, src + o * 32 + k4);
        }
    };

    // prologue
    gather(0);
    copyB(0, 0);
    CP_COMMIT();
    storeA(0, 0);

    for (int s = 0; s < slabs; s++) {
        int cur = s & 1;
        bool more = (s + 1 < slabs);
        if (more) {
            gather(s + 1);               // LDGs in flight during wait+MMA
            copyB(s + 1, cur ^ 1);
            CP_COMMIT();
            CP_WAIT1();
        } else {
            CP_WAIT0();
        }
        __syncthreads();

        const float* A  = smA + cur * A_FLOATS;
        const float* Bt = smB + cur * B_FLOATS;
        #pragma unroll
        for (int ks = 0; ks < 4; ks++) {
            int kb = ks * 8;
            uint32_t af[2][4], bf[8][2];
            #pragma unroll
            for (int mt = 0; mt < 2; mt++) {
                int r0 = wm * 32 + mt * 16 + g;
                af[mt][0] = __float_as_uint(A[r0 * ALD + kb + t]);
                af[mt][1] = __float_as_uint(A[(r0 + 8) * ALD + kb + t]);
                af[mt][2] = __float_as_uint(A[r0 * ALD + kb + 4 + t]);
                af[mt][3] = __float_as_uint(A[(r0 + 8) * ALD + kb + 4 + t]);
            }
            #pragma unroll
            for (int nt = 0; nt < 8; nt++) {
                int nc = wn * 64 + nt * 8 + g;
                bf[nt][0] = __float_as_uint(Bt[nc * ALD + kb + t]);
                bf[nt][1] = __float_as_uint(Bt[nc * ALD + kb + 4 + t]);
            }
            #pragma unroll
            for (int mt = 0; mt < 2; mt++)
                #pragma unroll
                for (int nt = 0; nt < 8; nt++)
                    mma1688(acc[mt][nt], af[mt][0], af[mt][1], af[mt][2], af[mt][3],
                            bf[nt][0], bf[nt][1]);
        }

        if (more) storeA(s + 1, cur ^ 1);
    }

    // ---- epilogue: +bias, float2 stores ----
    #pragma unroll
    for (int nt = 0; nt < 8; nt++) {
        int col = wn * 64 + nt * 8 + 2 * t;
        float bv0 = bias[col], bv1 = bias[col + 1];
        #pragma unroll
        for (int mt = 0; mt < 2; mt++) {
            int row = e0 + wm * 32 + mt * 16 + g;
            float2 v0 = make_float2(acc[mt][nt][0] + bv0, acc[mt][nt][1] + bv1);
            float2 v1 = make_float2(acc[mt][nt][2] + bv0, acc[mt][nt][3] + bv1);
            *(float2*)&Yout[((size_t)(b * E_ + row)) * ys + col] = v0;
            *(float2*)&Yout[((size_t)(b * E_ + row + 8)) * ys + col] = v1;
        }
    }
}

// ---------------- instance norm over E per (b,c) ----------------
__global__ void reduce_stats(const float* __restrict__ Z,
                             float* __restrict__ gsum, float* __restrict__ gssq)
{
    int b  = blockIdx.x >> 6;
    int ch = blockIdx.x & 63;
    int c  = threadIdx.x;
    const float* p = Z + ((size_t)(b * E_) + ch * 256) * 256 + c;
    float s = 0.f, q = 0.f;
    #pragma unroll 4
    for (int e = 0; e < 256; e++) {
        float v = p[(size_t)e * 256];
        s += v;
        q = fmaf(v, v, q);
    }
    atomicAdd(&gsum[b * 256 + c], s);
    atomicAdd(&gssq[b * 256 + c], q);
}

__global__ void finalize_stats(const float* __restrict__ gsum, const float* __restrict__ gssq,
                               float* __restrict__ mean, float* __restrict__ rstd)
{
    int i = blockIdx.x * blockDim.x + threadIdx.x;
    if (i < B_ * 256) {
        float m = gsum[i] * (1.f / E_);
        float v = gssq[i] * (1.f / E_) - m * m;
        mean[i] = m;
        rstd[i] = rsqrtf(v + 1e-5f);
    }
}

__global__ void apply_norm(const float* __restrict__ Z, const float* __restrict__ res,
                           const float* __restrict__ mean, const float* __restrict__ rstd,
                           float* __restrict__ out, int addres)
{
    size_t i = (size_t)blockIdx.x * blockDim.x + threadIdx.x;
    int b = (int)(i >> 20);
    int c = ((int)i & 63) * 4;
    float4 z = ((const float4*)Z)[i];
    int mi = b * 256 + c;
    float m0 = mean[mi], m1 = mean[mi + 1], m2 = mean[mi + 2], m3 = mean[mi + 3];
    float r0 = rstd[mi], r1 = rstd[mi + 1], r2 = rstd[mi + 2], r3 = rstd[mi + 3];
    float4 o;
    o.x = (z.x - m0) * r0;
    o.y = (z.y - m1) * r1;
    o.z = (z.z - m2) * r2;
    o.w = (z.w - m3) * r3;
    if (addres) {
        float4 rv = ((const float4*)res)[i];
        o.x += rv.x; o.y += rv.y; o.z += rv.z; o.w += rv.w;
    }
    o.x = fmaxf(o.x, 0.f);
    o.y = fmaxf(o.y, 0.f);
    o.z = fmaxf(o.z, 0.f);
    o.w = fmaxf(o.w, 0.f);
    ((float4*)out)[i] = o;
}

// ---------------- host ----------------
extern "C" void kernel_launch(void* const* d_in, const int* in_sizes, int n_in,
                              void* d_out, int out_size)
{
    const float* from_up   = (const float*)d_in[0];
    const float* from_down = (const float*)d_in[1];
    const int*   ei        = (const int*)  d_in[2];
    const float* W_up = (const float*)d_in[3];
    const float* b_up = (const float*)d_in[4];
    const float* W1   = (const float*)d_in[5];
    const float* b1   = (const float*)d_in[6];
    const float* W2a  = (const float*)d_in[7];
    const float* b2a  = (const float*)d_in[8];
    const float* W2b  = (const float*)d_in[9];
    const float* b2b  = (const float*)d_in[10];
    float* out = (float*)d_out;

    float *U, *X, *Z, *X1, *X2, *Wup, *W1r, *W2ar, *W2br, *sum_, *ssq_, *mean_, *rstd_;
    cudaGetSymbolAddress((void**)&U,    g_U);
    cudaGetSymbolAddress((void**)&X,    g_X);
    cudaGetSymbolAddress((void**)&Z,    g_Z);
    cudaGetSymbolAddress((void**)&X1,   g_X1);
    cudaGetSymbolAddress((void**)&X2,   g_X2);
    cudaGetSymbolAddress((void**)&Wup,  g_Wup);
    cudaGetSymbolAddress((void**)&W1r,  g_W1r);
    cudaGetSymbolAddress((void**)&W2ar, g_W2ar);
    cudaGetSymbolAddress((void**)&W2br, g_W2br);
    cudaGetSymbolAddress((void**)&sum_,  g_sum);
    cudaGetSymbolAddress((void**)&ssq_,  g_ssq);
    cudaGetSymbolAddress((void**)&mean_, g_mean);
    cudaGetSymbolAddress((void**)&rstd_, g_rstd);

    cudaFuncSetAttribute(gconv_mma, cudaFuncAttributeMaxDynamicSharedMemorySize, SMEM_BYTES);

    // weight images ([slab][o][k32], kind-paired, tf32-rounded)
    prep_w_img<<<(5 *  4 * 8192 + 255) / 256, 256>>>(W_up, Wup, 128);
    prep_w_img<<<(5 * 16 * 8192 + 255) / 256, 256>>>(W1,   W1r, 512);
    prep_w_img<<<(5 *  8 * 8192 + 255) / 256, 256>>>(W2a,  W2ar, 256);
    prep_w_img<<<(5 *  8 * 8192 + 255) / 256, 256>>>(W2b,  W2br, 256);

    dim3 tb(32, 8);
    trans_ce_ec<<<dim3(E_ / 32, 128 / 32, B_), tb>>>(from_up,   U, 128, 128, 0);
    trans_ce_ec<<<dim3(E_ / 32, 256 / 32, B_), tb>>>(from_down, X, 256, 512, 256);

    dim3 cg(E_ / 128, 1, B_);
    // conv1: writes concat cols 0..255 of X
    gconv_mma<<<cg, 512, SMEM_BYTES>>>(U, 128, ei, Wup, b_up, X, 512);
    // conv2 over concat
    gconv_mma<<<cg, 512, SMEM_BYTES>>>(X, 512, ei, W1r, b1, Z, 256);

    // norm1 -> X1
    cudaMemsetAsync(sum_, 0, B_ * 256 * 4);
    cudaMemsetAsync(ssq_, 0, B_ * 256 * 4);
    reduce_stats<<<B_ * 64, 256>>>(Z, sum_, ssq_);
    finalize_stats<<<(B_ * 256 + 255) / 256, 256>>>(sum_, ssq_, mean_, rstd_);
    apply_norm<<<32768, 256>>>(Z, Z, mean_, rstd_, X1, 0);

    // residual block A
    gconv_mma<<<cg, 512, SMEM_BYTES>>>(X1, 256, ei, W2ar, b2a, Z, 256);
    cudaMemsetAsync(sum_, 0, B_ * 256 * 4);
    cudaMemsetAsync(ssq_, 0, B_ * 256 * 4);
    reduce_stats<<<B_ * 64, 256>>>(Z, sum_, ssq_);
    finalize_stats<<<(B_ * 256 + 255) / 256, 256>>>(sum_, ssq_, mean_, rstd_);
    apply_norm<<<32768, 256>>>(Z, X1, mean_, rstd_, X2, 1);

    // residual block B
    gconv_mma<<<cg, 512, SMEM_BYTES>>>(X2, 256, ei, W2br, b2b, Z, 256);
    cudaMemsetAsync(sum_, 0, B_ * 256 * 4);
    cudaMemsetAsync(ssq_, 0, B_ * 256 * 4);
    reduce_stats<<<B_ * 64, 256>>>(Z, sum_, ssq_);
    finalize_stats<<<(B_ * 256 + 255) / 256, 256>>>(sum_, ssq_, mean_, rstd_);
    apply_norm<<<32768, 256>>>(Z, X2, mean_, rstd_, X1, 1);

    // final layout [B,256,E]
    trans_ec_ce<<<dim3(E_ / 32, 256 / 32, B_), tb>>>(X1, out);
}

// round 6
// speedup vs baseline: 4.0903x; 1.4578x over previous
#include <cuda_runtime.h>
#include <cuda_fp16.h>
#include <cuda_bf16.h>
#include <math.h>
#include <stdint.h>

#define B_ 8
#define E_ 16384
#define O_ 256

// ---------------- scratch (__device__ globals; no allocs allowed) ----------------
__device__ float g_U [(size_t)B_*E_*128];   // from_up, edge-major
__device__ float g_X [(size_t)B_*E_*512];   // concat(conv1, from_down), edge-major
__device__ float g_Z [(size_t)B_*E_*256];   // conv output (pre-norm)
__device__ float g_X1[(size_t)B_*E_*256];
__device__ float g_X2[(size_t)B_*E_*256];
__device__ __half g_Wup [5*128*256];
__device__ __half g_W1r [5*512*256];
__device__ __half g_W2ar[5*256*256];
__device__ __half g_W2br[5*256*256];
__device__ float g_sum [B_*256];
__device__ float g_ssq [B_*256];
__device__ float g_mean[B_*256];
__device__ float g_rstd[B_*256];

__device__ __forceinline__ uint32_t smem_u32(const void* p) {
    uint32_t a;
    asm("{ .reg .u64 t; cvta.to.shared.u64 t, %1; cvt.u32.u64 %0, t; }" : "=r"(a) : "l"(p));
    return a;
}
#define CP_ASYNC16(dst, src) \
    asm volatile("cp.async.cg.shared.global [%0], [%1], 16;" :: "r"(dst), "l"(src))
#define CP_COMMIT() asm volatile("cp.async.commit_group;" ::: "memory")
#define CP_WAIT2()  asm volatile("cp.async.wait_group 2;" ::: "memory")
#define LDSM_X4(r0, r1, r2, r3, addr) \
    asm volatile("ldmatrix.sync.aligned.m8n8.x4.shared.b16 {%0,%1,%2,%3}, [%4];" \
        : "=r"(r0), "=r"(r1), "=r"(r2), "=r"(r3) : "r"(addr))

__device__ __forceinline__ void mma16816(float* d, const uint32_t* a, const uint32_t* b)
{
    asm volatile(
        "mma.sync.aligned.m16n8k16.row.col.f32.f16.f16.f32 "
        "{%0,%1,%2,%3}, {%4,%5,%6,%7}, {%8,%9}, {%0,%1,%2,%3};"
        : "+f"(d[0]), "+f"(d[1]), "+f"(d[2]), "+f"(d[3])
        : "r"(a[0]), "r"(a[1]), "r"(a[2]), "r"(a[3]), "r"(b[0]), "r"(b[1]));
}

__device__ __forceinline__ uint32_t h2u(float x, float y) {
    __half2 h = __floats2half2_rn(x, y);
    return *reinterpret_cast<uint32_t*>(&h);
}

// ---------------- slab map ----------------
// slab s (32 K-rows): cc = s/5, r = s%5
//  r=0: kind0 (center), channels [32cc, +32)
//  r=1: pair(1,3) chunk [32cc, +16)      rows 0-15 = n1+n3, rows 16-31 = |n1-n3|
//  r=2: pair(1,3) chunk [32cc+16, +16)
//  r=3: pair(2,4) chunk [32cc, +16)
//  r=4: pair(2,4) chunk [32cc+16, +16)

// ---------------- weight image prep: W[o,c,kk] -> [slab][o 0..255][k32], fp16 ----------------
__global__ void prep_w_img(const float* __restrict__ W, __half* __restrict__ Wimg, int C)
{
    int i = blockIdx.x * blockDim.x + threadIdx.x;
    int total = 5 * (C / 32) * 8192;
    if (i >= total) return;
    int slab   = i >> 13;
    int within = i & 8191;
    int o = within >> 5;
    int k = within & 31;
    int cc = slab / 5, r = slab % 5;
    int kind, c;
    if (r == 0) {
        kind = 0; c = 32 * cc + k;
    } else {
        int base  = (r <= 2) ? 1 : 2;
        int pairc = 32 * cc + ((r == 2 || r == 4) ? 16 : 0);
        if (k < 16) { kind = base;     c = pairc + k; }
        else        { kind = base + 2; c = pairc + k - 16; }
    }
    Wimg[i] = __float2half_rn(W[(o * C + c) * 5 + kind]);
}

// ---------------- transpose [B,C,E] -> [B,E,os] ----------------
__global__ void trans_ce_ec(const float* __restrict__ in, float* __restrict__ out,
                            int C, int os, int coff)
{
    __shared__ float tile[32][33];
    int b  = blockIdx.z;
    int e0 = blockIdx.x * 32, c0 = blockIdx.y * 32;
    const float* ip = in + ((size_t)b * C + c0) * E_ + e0;
    #pragma unroll
    for (int i = threadIdx.y; i < 32; i += 8)
        tile[i][threadIdx.x] = ip[(size_t)i * E_ + threadIdx.x];
    __syncthreads();
    float* op = out + ((size_t)(b * E_ + e0)) * os + coff + c0;
    #pragma unroll
    for (int i = threadIdx.y; i < 32; i += 8)
        op[(size_t)i * os + threadIdx.x] = tile[threadIdx.x][i];
}

// ---------------- transpose [B,E,256] -> [B,256,E] ----------------
__global__ void trans_ec_ce(const float* __restrict__ in, float* __restrict__ out)
{
    __shared__ float tile[32][33];
    int b  = blockIdx.z;
    int e0 = blockIdx.x * 32, c0 = blockIdx.y * 32;
    const float* ip = in + ((size_t)(b * E_ + e0)) * 256 + c0;
    #pragma unroll
    for (int i = threadIdx.y; i < 32; i += 8)
        tile[i][threadIdx.x] = ip[(size_t)i * 256 + threadIdx.x];
    __syncthreads();
    float* op = out + ((size_t)(b * 256 + c0)) * E_ + e0;
    #pragma unroll
    for (int i = threadIdx.y; i < 32; i += 8)
        op[(size_t)i * E_ + threadIdx.x] = tile[threadIdx.x][i];
}

// ---------------- fused gather + fp16 tensor-core GEMM ----------------
// Block: 128 edges x 256 outs, 512 threads (16 warps, 4x4: warp tile 32x64).
// A: 2-stage STS buffer (safe: writes sit between the surrounding barriers).
// B: 4-stage cp.async ring, issue slab s+2 at iter s, wait_group 2.
//    (fixes the R5 WAR race: writers of stage (s+2)%4 have passed SYNC(s-1);
//     its last readers (iter s-2) finished before SYNC(s-1).)
#define ALD 40                         // row stride in halves (80 B, 16B-aligned rows)
#define A_HALFS (128 * ALD)            // 5120
#define B_HALFS (256 * ALD)            // 10240
#define A_BYTES (A_HALFS * 2)          // 10240
#define B_BYTES (B_HALFS * 2)          // 20480
#define SMEM_BYTES (2 * A_BYTES + 4 * B_BYTES + 512 * 4)   // 104448

__global__ __launch_bounds__(512)
void gconv_mma(const float* __restrict__ Xin, int C,
               const int* __restrict__ ei,
               const __half* __restrict__ Wimg,
               const float* __restrict__ bias,
               float* __restrict__ Yout, int ys)
{
    extern __shared__ __half smh[];
    __half* smA = smh;                          // 2 stages
    __half* smB = smh + 2 * A_HALFS;            // 4 stages
    int*    snb = (int*)(smh + 2 * A_HALFS + 4 * B_HALFS);
    const uint32_t sA_u32 = smem_u32(smA);
    const uint32_t sB_u32 = smem_u32(smB);

    const int tid  = threadIdx.x;
    const int wid  = tid >> 5;
    const int lane = tid & 31;
    const int g = lane >> 2;
    const int t = lane & 3;
    const int wm = wid >> 2;     // 0..3: 32-edge quarter
    const int wn = wid & 3;      // 0..3: 64-out quarter
    const int b  = blockIdx.z;
    const int e0 = blockIdx.x * 128;

    {
        const int* eip = ei + ((size_t)(b * E_) + e0) * 4;
        snb[tid] = (b * E_ + eip[tid]) * C;
    }
    __syncthreads();

    const int x0base = (b * E_ + e0) * C;
    const int slabs  = 5 * (C / 32);

    float acc[2][8][4];
    #pragma unroll
    for (int mt = 0; mt < 2; mt++)
        #pragma unroll
        for (int nt = 0; nt < 8; nt++)
            #pragma unroll
            for (int rr = 0; rr < 4; rr++) acc[mt][nt][rr] = 0.f;

    float4 ga[2];

    auto gather = [&](int s) {
        int cc = s / 5, r = s % 5;
        if (r == 0) {
            #pragma unroll
            for (int j = 0; j < 2; j++) {
                int v = tid + j * 512;
                int edge = v >> 3, c4 = (v & 7) * 4;
                ga[j] = *(const float4*)&Xin[x0base + edge * C + 32 * cc + c4];
            }
        } else {
            int na = (r <= 2) ? 0 : 1;
            int pc = 32 * cc + ((r == 2 || r == 4) ? 16 : 0);
            int edge = tid >> 2, c4 = (tid & 3) * 4;
            int c = pc + c4;
            float4 p = *(const float4*)&Xin[snb[edge * 4 + na] + c];
            float4 q = *(const float4*)&Xin[snb[edge * 4 + na + 2] + c];
            ga[0] = make_float4(p.x + q.x, p.y + q.y, p.z + q.z, p.w + q.w);
            ga[1] = make_float4(fabsf(p.x - q.x), fabsf(p.y - q.y),
                                fabsf(p.z - q.z), fabsf(p.w - q.w));
        }
    };
    auto storeA = [&](int s, int buf) {
        __half* A = smA + buf * A_HALFS;
        int r = s % 5;
        if (r == 0) {
            #pragma unroll
            for (int j = 0; j < 2; j++) {
                int v = tid + j * 512;
                int edge = v >> 3, k = (v & 7) * 4;
                float4 a = ga[j];
                *(uint2*)&A[edge * ALD + k] = make_uint2(h2u(a.x, a.y), h2u(a.z, a.w));
            }
        } else {
            int edge = tid >> 2, k = (tid & 3) * 4;
            float4 sv = ga[0], dv = ga[1];
            *(uint2*)&A[edge * ALD + k]      = make_uint2(h2u(sv.x, sv.y), h2u(sv.z, sv.w));
            *(uint2*)&A[edge * ALD + 16 + k] = make_uint2(h2u(dv.x, dv.y), h2u(dv.z, dv.w));
        }
    };
    auto copyB = [&](int s, int stage) {
        const __half* src = Wimg + (size_t)s * 8192;
        uint32_t dstb = sB_u32 + stage * B_BYTES;
        #pragma unroll
        for (int j = 0; j < 2; j++) {
            int idx = tid + j * 512;
            int o = idx >> 2, seg = (idx & 3) * 8;   // halves
            CP_ASYNC16(dstb + (uint32_t)(o * ALD + seg) * 2, src + o * 32 + seg);
        }
    };

    // prologue: pre-issue B slabs 0 and 1; gather+store A slab 0
    copyB(0, 0);
    CP_COMMIT();
    copyB(1, 1);
    CP_COMMIT();
    gather(0);
    storeA(0, 0);

    for (int s = 0; s < slabs; s++) {
        bool more = (s + 1 < slabs);
        // issue B slab s+2 (stage (s+2)%4) — safe per ring proof
        if (s + 2 < slabs) copyB(s + 2, (s + 2) & 3);
        CP_COMMIT();                    // always commit: keeps group arithmetic constant
        if (more) gather(s + 1);        // LDGs in flight during wait+MMA
        CP_WAIT2();                     // g_s complete (g_{s+1}, g_{s+2} may be in flight)
        __syncthreads();

        const uint32_t Abase = sA_u32 + (s & 1) * A_BYTES;
        const uint32_t Bbase = sB_u32 + (s & 3) * B_BYTES;
        #pragma unroll
        for (int ks = 0; ks < 2; ks++) {
            uint32_t af[2][4], bf[8][2];
            #pragma unroll
            for (int mt = 0; mt < 2; mt++) {
                int row = wm * 32 + mt * 16 + (lane & 15);
                int kof = ks * 16 + ((lane & 16) ? 8 : 0);
                LDSM_X4(af[mt][0], af[mt][1], af[mt][2], af[mt][3],
                        Abase + (uint32_t)(row * ALD + kof) * 2);
            }
            #pragma unroll
            for (int np = 0; np < 4; np++) {
                int nrow = wn * 64 + np * 16 + (lane & 7) + ((lane & 16) ? 8 : 0);
                int kof  = ks * 16 + ((lane & 8) ? 8 : 0);
                LDSM_X4(bf[2 * np][0], bf[2 * np][1], bf[2 * np + 1][0], bf[2 * np + 1][1],
                        Bbase + (uint32_t)(nrow * ALD + kof) * 2);
            }
            #pragma unroll
            for (int mt = 0; mt < 2; mt++)
                #pragma unroll
                for (int nt = 0; nt < 8; nt++)
                    mma16816(acc[mt][nt], af[mt], bf[nt]);
        }

        if (more) storeA(s + 1, (s + 1) & 1);   // after SYNC(s): safe vs iter s-1 readers
    }

    // ---- epilogue: +bias, float2 stores ----
    #pragma unroll
    for (int nt = 0; nt < 8; nt++) {
        int col = wn * 64 + nt * 8 + 2 * t;
        float bv0 = bias[col], bv1 = bias[col + 1];
        #pragma unroll
        for (int mt = 0; mt < 2; mt++) {
            int row = e0 + wm * 32 + mt * 16 + g;
            float2 v0 = make_float2(acc[mt][nt][0] + bv0, acc[mt][nt][1] + bv1);
            float2 v1 = make_float2(acc[mt][nt][2] + bv0, acc[mt][nt][3] + bv1);
            *(float2*)&Yout[((size_t)(b * E_ + row)) * ys + col] = v0;
            *(float2*)&Yout[((size_t)(b * E_ + row + 8)) * ys + col] = v1;
        }
    }
}

// ---------------- instance norm over E per (b,c) ----------------
__global__ void reduce_stats(const float* __restrict__ Z,
                             float* __restrict__ gsum, float* __restrict__ gssq)
{
    int b  = blockIdx.x >> 6;
    int ch = blockIdx.x & 63;
    int c  = threadIdx.x;
    const float* p = Z + ((size_t)(b * E_) + ch * 256) * 256 + c;
    float s = 0.f, q = 0.f;
    #pragma unroll 4
    for (int e = 0; e < 256; e++) {
        float v = p[(size_t)e * 256];
        s += v;
        q = fmaf(v, v, q);
    }
    atomicAdd(&gsum[b * 256 + c], s);
    atomicAdd(&gssq[b * 256 + c], q);
}

__global__ void finalize_stats(const float* __restrict__ gsum, const float* __restrict__ gssq,
                               float* __restrict__ mean, float* __restrict__ rstd)
{
    int i = blockIdx.x * blockDim.x + threadIdx.x;
    if (i < B_ * 256) {
        float m = gsum[i] * (1.f / E_);
        float v = gssq[i] * (1.f / E_) - m * m;
        mean[i] = m;
        rstd[i] = rsqrtf(v + 1e-5f);
    }
}

__global__ void apply_norm(const float* __restrict__ Z, const float* __restrict__ res,
                           const float* __restrict__ mean, const float* __restrict__ rstd,
                           float* __restrict__ out, int addres)
{
    size_t i = (size_t)blockIdx.x * blockDim.x + threadIdx.x;
    int b = (int)(i >> 20);
    int c = ((int)i & 63) * 4;
    float4 z = ((const float4*)Z)[i];
    int mi = b * 256 + c;
    float m0 = mean[mi], m1 = mean[mi + 1], m2 = mean[mi + 2], m3 = mean[mi + 3];
    float r0 = rstd[mi], r1 = rstd[mi + 1], r2 = rstd[mi + 2], r3 = rstd[mi + 3];
    float4 o;
    o.x = (z.x - m0) * r0;
    o.y = (z.y - m1) * r1;
    o.z = (z.z - m2) * r2;
    o.w = (z.w - m3) * r3;
    if (addres) {
        float4 rv = ((const float4*)res)[i];
        o.x += rv.x; o.y += rv.y; o.z += rv.z; o.w += rv.w;
    }
    o.x = fmaxf(o.x, 0.f);
    o.y = fmaxf(o.y, 0.f);
    o.z = fmaxf(o.z, 0.f);
    o.w = fmaxf(o.w, 0.f);
    ((float4*)out)[i] = o;
}

// ---------------- host ----------------
extern "C" void kernel_launch(void* const* d_in, const int* in_sizes, int n_in,
                              void* d_out, int out_size)
{
    const float* from_up   = (const float*)d_in[0];
    const float* from_down = (const float*)d_in[1];
    const int*   ei        = (const int*)  d_in[2];
    const float* W_up = (const float*)d_in[3];
    const float* b_up = (const float*)d_in[4];
    const float* W1   = (const float*)d_in[5];
    const float* b1   = (const float*)d_in[6];
    const float* W2a  = (const float*)d_in[7];
    const float* b2a  = (const float*)d_in[8];
    const float* W2b  = (const float*)d_in[9];
    const float* b2b  = (const float*)d_in[10];
    float* out = (float*)d_out;

    float *U, *X, *Z, *X1, *X2, *sum_, *ssq_, *mean_, *rstd_;
    __half *Wup, *W1r, *W2ar, *W2br;
    cudaGetSymbolAddress((void**)&U,    g_U);
    cudaGetSymbolAddress((void**)&X,    g_X);
    cudaGetSymbolAddress((void**)&Z,    g_Z);
    cudaGetSymbolAddress((void**)&X1,   g_X1);
    cudaGetSymbolAddress((void**)&X2,   g_X2);
    cudaGetSymbolAddress((void**)&Wup,  g_Wup);
    cudaGetSymbolAddress((void**)&W1r,  g_W1r);
    cudaGetSymbolAddress((void**)&W2ar, g_W2ar);
    cudaGetSymbolAddress((void**)&W2br, g_W2br);
    cudaGetSymbolAddress((void**)&sum_,  g_sum);
    cudaGetSymbolAddress((void**)&ssq_,  g_ssq);
    cudaGetSymbolAddress((void**)&mean_, g_mean);
    cudaGetSymbolAddress((void**)&rstd_, g_rstd);

    cudaFuncSetAttribute(gconv_mma, cudaFuncAttributeMaxDynamicSharedMemorySize, SMEM_BYTES);

    // weight images ([slab][o][k32], kind-paired, fp16)
    prep_w_img<<<(5 *  4 * 8192 + 255) / 256, 256>>>(W_up, Wup, 128);
    prep_w_img<<<(5 * 16 * 8192 + 255) / 256, 256>>>(W1,   W1r, 512);
    prep_w_img<<<(5 *  8 * 8192 + 255) / 256, 256>>>(W2a,  W2ar, 256);
    prep_w_img<<<(5 *  8 * 8192 + 255) / 256, 256>>>(W2b,  W2br, 256);

    dim3 tb(32, 8);
    trans_ce_ec<<<dim3(E_ / 32, 128 / 32, B_), tb>>>(from_up,   U, 128, 128, 0);
    trans_ce_ec<<<dim3(E_ / 32, 256 / 32, B_), tb>>>(from_down, X, 256, 512, 256);

    dim3 cg(E_ / 128, 1, B_);
    // conv1: writes concat cols 0..255 of X
    gconv_mma<<<cg, 512, SMEM_BYTES>>>(U, 128, ei, Wup, b_up, X, 512);
    // conv2 over concat
    gconv_mma<<<cg, 512, SMEM_BYTES>>>(X, 512, ei, W1r, b1, Z, 256);

    // norm1 -> X1
    cudaMemsetAsync(sum_, 0, B_ * 256 * 4);
    cudaMemsetAsync(ssq_, 0, B_ * 256 * 4);
    reduce_stats<<<B_ * 64, 256>>>(Z, sum_, ssq_);
    finalize_stats<<<(B_ * 256 + 255) / 256, 256>>>(sum_, ssq_, mean_, rstd_);
    apply_norm<<<32768, 256>>>(Z, Z, mean_, rstd_, X1, 0);

    // residual block A
    gconv_mma<<<cg, 512, SMEM_BYTES>>>(X1, 256, ei, W2ar, b2a, Z, 256);
    cudaMemsetAsync(sum_, 0, B_ * 256 * 4);
    cudaMemsetAsync(ssq_, 0, B_ * 256 * 4);
    reduce_stats<<<B_ * 64, 256>>>(Z, sum_, ssq_);
    finalize_stats<<<(B_ * 256 + 255) / 256, 256>>>(sum_, ssq_, mean_, rstd_);
    apply_norm<<<32768, 256>>>(Z, X1, mean_, rstd_, X2, 1);

    // residual block B
    gconv_mma<<<cg, 512, SMEM_BYTES>>>(X2, 256, ei, W2br, b2b, Z, 256);
    cudaMemsetAsync(sum_, 0, B_ * 256 * 4);
    cudaMemsetAsync(ssq_, 0, B_ * 256 * 4);
    reduce_stats<<<B_ * 64, 256>>>(Z, sum_, ssq_);
    finalize_stats<<<(B_ * 256 + 255) / 256, 256>>>(sum_, ssq_, mean_, rstd_);
    apply_norm<<<32768, 256>>>(Z, X2, mean_, rstd_, X1, 1);

    // final layout [B,256,E]
    trans_ec_ce<<<dim3(E_ / 32, 256 / 32, B_), tb>>>(X1, out);
}

// round 7
// speedup vs baseline: 4.2275x; 1.0335x over previous
#include <cuda_runtime.h>
#include <cuda_fp16.h>
#include <cuda_bf16.h>
#include <math.h>
#include <stdint.h>

#define B_ 8
#define E_ 16384
#define O_ 256

// ---------------- scratch (__device__ globals; no allocs allowed) ----------------
__device__ float g_U [(size_t)B_*E_*128];   // from_up, edge-major
__device__ float g_X [(size_t)B_*E_*512];   // concat(conv1, from_down), edge-major
__device__ float g_Z [(size_t)B_*E_*256];   // conv output (pre-norm)
__device__ float g_X1[(size_t)B_*E_*256];
__device__ float g_X2[(size_t)B_*E_*256];
__device__ __half g_Wup [5*128*256];
__device__ __half g_W1r [5*512*256];
__device__ __half g_W2ar[5*256*256];
__device__ __half g_W2br[5*256*256];
__device__ float g_sum [B_*256];
__device__ float g_ssq [B_*256];
__device__ float g_mean[B_*256];
__device__ float g_rstd[B_*256];

__device__ __forceinline__ uint32_t smem_u32(const void* p) {
    uint32_t a;
    asm("{ .reg .u64 t; cvta.to.shared.u64 t, %1; cvt.u32.u64 %0, t; }" : "=r"(a) : "l"(p));
    return a;
}
#define CP_ASYNC16(dst, src) \
    asm volatile("cp.async.cg.shared.global [%0], [%1], 16;" :: "r"(dst), "l"(src))
#define CP_COMMIT() asm volatile("cp.async.commit_group;" ::: "memory")
#define CP_WAIT2()  asm volatile("cp.async.wait_group 2;" ::: "memory")
#define LDSM_X4(r0, r1, r2, r3, addr) \
    asm volatile("ldmatrix.sync.aligned.m8n8.x4.shared.b16 {%0,%1,%2,%3}, [%4];" \
        : "=r"(r0), "=r"(r1), "=r"(r2), "=r"(r3) : "r"(addr))

__device__ __forceinline__ void mma16816(float* d, const uint32_t* a, const uint32_t* b)
{
    asm volatile(
        "mma.sync.aligned.m16n8k16.row.col.f32.f16.f16.f32 "
        "{%0,%1,%2,%3}, {%4,%5,%6,%7}, {%8,%9}, {%0,%1,%2,%3};"
        : "+f"(d[0]), "+f"(d[1]), "+f"(d[2]), "+f"(d[3])
        : "r"(a[0]), "r"(a[1]), "r"(a[2]), "r"(a[3]), "r"(b[0]), "r"(b[1]));
}

__device__ __forceinline__ uint32_t h2u(float x, float y) {
    __half2 h = __floats2half2_rn(x, y);
    return *reinterpret_cast<uint32_t*>(&h);
}

// ---------------- slab map ----------------
// slab s (32 K-rows): cc = s/5, r = s%5
//  r=0: kind0 (center), channels [32cc, +32)
//  r=1: pair(1,3) chunk [32cc, +16)      rows 0-15 = n1+n3, rows 16-31 = |n1-n3|
//  r=2: pair(1,3) chunk [32cc+16, +16)
//  r=3: pair(2,4) chunk [32cc, +16)
//  r=4: pair(2,4) chunk [32cc+16, +16)

// ---------------- weight image prep: W[o,c,kk] -> [slab][o 0..255][k32], fp16 ----------------
__global__ void prep_w_img(const float* __restrict__ W, __half* __restrict__ Wimg, int C)
{
    int i = blockIdx.x * blockDim.x + threadIdx.x;
    int total = 5 * (C / 32) * 8192;
    if (i >= total) return;
    int slab   = i >> 13;
    int within = i & 8191;
    int o = within >> 5;
    int k = within & 31;
    int cc = slab / 5, r = slab % 5;
    int kind, c;
    if (r == 0) {
        kind = 0; c = 32 * cc + k;
    } else {
        int base  = (r <= 2) ? 1 : 2;
        int pairc = 32 * cc + ((r == 2 || r == 4) ? 16 : 0);
        if (k < 16) { kind = base;     c = pairc + k; }
        else        { kind = base + 2; c = pairc + k - 16; }
    }
    Wimg[i] = __float2half_rn(W[(o * C + c) * 5 + kind]);
}

// ---------------- transpose [B,C,E] -> [B,E,os] ----------------
__global__ void trans_ce_ec(const float* __restrict__ in, float* __restrict__ out,
                            int C, int os, int coff)
{
    __shared__ float tile[32][33];
    int b  = blockIdx.z;
    int e0 = blockIdx.x * 32, c0 = blockIdx.y * 32;
    const float* ip = in + ((size_t)b * C + c0) * E_ + e0;
    #pragma unroll
    for (int i = threadIdx.y; i < 32; i += 8)
        tile[i][threadIdx.x] = ip[(size_t)i * E_ + threadIdx.x];
    __syncthreads();
    float* op = out + ((size_t)(b * E_ + e0)) * os + coff + c0;
    #pragma unroll
    for (int i = threadIdx.y; i < 32; i += 8)
        op[(size_t)i * os + threadIdx.x] = tile[threadIdx.x][i];
}

// ---------------- fused gather + fp16 tensor-core GEMM (+ optional stats) ----------------
// Block: 128 edges x 256 outs, 512 threads (16 warps, 4x4: warp tile 32x64).
// A: 2-stage STS buffer. B: 4-stage cp.async ring (issue s+2, wait_group 2).
// Epilogue optionally accumulates per-channel sum/ssq into gsum/gssq (instnorm).
#define ALD 40                         // row stride in halves (80 B, 16B-aligned rows)
#define A_HALFS (128 * ALD)            // 5120
#define B_HALFS (256 * ALD)            // 10240
#define A_BYTES (A_HALFS * 2)          // 10240
#define B_BYTES (B_HALFS * 2)          // 20480
#define SMEM_BYTES (2 * A_BYTES + 4 * B_BYTES + 512 * 4)   // 104448

__global__ __launch_bounds__(512)
void gconv_mma(const float* __restrict__ Xin, int C,
               const int* __restrict__ ei,
               const __half* __restrict__ Wimg,
               const float* __restrict__ bias,
               float* __restrict__ Yout, int ys,
               float* __restrict__ gsum, float* __restrict__ gssq)
{
    extern __shared__ __half smh[];
    __half* smA = smh;                          // 2 stages
    __half* smB = smh + 2 * A_HALFS;            // 4 stages
    int*    snb = (int*)(smh + 2 * A_HALFS + 4 * B_HALFS);
    const uint32_t sA_u32 = smem_u32(smA);
    const uint32_t sB_u32 = smem_u32(smB);

    const int tid  = threadIdx.x;
    const int wid  = tid >> 5;
    const int lane = tid & 31;
    const int g = lane >> 2;
    const int t = lane & 3;
    const int wm = wid >> 2;     // 0..3: 32-edge quarter
    const int wn = wid & 3;      // 0..3: 64-out quarter
    const int b  = blockIdx.z;
    const int e0 = blockIdx.x * 128;

    {
        const int* eip = ei + ((size_t)(b * E_) + e0) * 4;
        snb[tid] = (b * E_ + eip[tid]) * C;
    }
    __syncthreads();

    const int x0base = (b * E_ + e0) * C;
    const int slabs  = 5 * (C / 32);

    float acc[2][8][4];
    #pragma unroll
    for (int mt = 0; mt < 2; mt++)
        #pragma unroll
        for (int nt = 0; nt < 8; nt++)
            #pragma unroll
            for (int rr = 0; rr < 4; rr++) acc[mt][nt][rr] = 0.f;

    float4 ga[2];

    auto gather = [&](int s) {
        int cc = s / 5, r = s % 5;
        if (r == 0) {
            #pragma unroll
            for (int j = 0; j < 2; j++) {
                int v = tid + j * 512;
                int edge = v >> 3, c4 = (v & 7) * 4;
                ga[j] = *(const float4*)&Xin[x0base + edge * C + 32 * cc + c4];
            }
        } else {
            int na = (r <= 2) ? 0 : 1;
            int pc = 32 * cc + ((r == 2 || r == 4) ? 16 : 0);
            int edge = tid >> 2, c4 = (tid & 3) * 4;
            int c = pc + c4;
            float4 p = *(const float4*)&Xin[snb[edge * 4 + na] + c];
            float4 q = *(const float4*)&Xin[snb[edge * 4 + na + 2] + c];
            ga[0] = make_float4(p.x + q.x, p.y + q.y, p.z + q.z, p.w + q.w);
            ga[1] = make_float4(fabsf(p.x - q.x), fabsf(p.y - q.y),
                                fabsf(p.z - q.z), fabsf(p.w - q.w));
        }
    };
    auto storeA = [&](int s, int buf) {
        __half* A = smA + buf * A_HALFS;
        int r = s % 5;
        if (r == 0) {
            #pragma unroll
            for (int j = 0; j < 2; j++) {
                int v = tid + j * 512;
                int edge = v >> 3, k = (v & 7) * 4;
                float4 a = ga[j];
                *(uint2*)&A[edge * ALD + k] = make_uint2(h2u(a.x, a.y), h2u(a.z, a.w));
            }
        } else {
            int edge = tid >> 2, k = (tid & 3) * 4;
            float4 sv = ga[0], dv = ga[1];
            *(uint2*)&A[edge * ALD + k]      = make_uint2(h2u(sv.x, sv.y), h2u(sv.z, sv.w));
            *(uint2*)&A[edge * ALD + 16 + k] = make_uint2(h2u(dv.x, dv.y), h2u(dv.z, dv.w));
        }
    };
    auto copyB = [&](int s, int stage) {
        const __half* src = Wimg + (size_t)s * 8192;
        uint32_t dstb = sB_u32 + stage * B_BYTES;
        #pragma unroll
        for (int j = 0; j < 2; j++) {
            int idx = tid + j * 512;
            int o = idx >> 2, seg = (idx & 3) * 8;   // halves
            CP_ASYNC16(dstb + (uint32_t)(o * ALD + seg) * 2, src + o * 32 + seg);
        }
    };

    // prologue: pre-issue B slabs 0 and 1; gather+store A slab 0
    copyB(0, 0);
    CP_COMMIT();
    copyB(1, 1);
    CP_COMMIT();
    gather(0);
    storeA(0, 0);

    for (int s = 0; s < slabs; s++) {
        bool more = (s + 1 < slabs);
        if (s + 2 < slabs) copyB(s + 2, (s + 2) & 3);
        CP_COMMIT();                    // always commit: keeps group arithmetic constant
        if (more) gather(s + 1);        // LDGs in flight during wait+MMA
        CP_WAIT2();
        __syncthreads();

        const uint32_t Abase = sA_u32 + (s & 1) * A_BYTES;
        const uint32_t Bbase = sB_u32 + (s & 3) * B_BYTES;
        #pragma unroll
        for (int ks = 0; ks < 2; ks++) {
            uint32_t af[2][4], bf[8][2];
            #pragma unroll
            for (int mt = 0; mt < 2; mt++) {
                int row = wm * 32 + mt * 16 + (lane & 15);
                int kof = ks * 16 + ((lane & 16) ? 8 : 0);
                LDSM_X4(af[mt][0], af[mt][1], af[mt][2], af[mt][3],
                        Abase + (uint32_t)(row * ALD + kof) * 2);
            }
            #pragma unroll
            for (int np = 0; np < 4; np++) {
                int nrow = wn * 64 + np * 16 + (lane & 7) + ((lane & 16) ? 8 : 0);
                int kof  = ks * 16 + ((lane & 8) ? 8 : 0);
                LDSM_X4(bf[2 * np][0], bf[2 * np][1], bf[2 * np + 1][0], bf[2 * np + 1][1],
                        Bbase + (uint32_t)(nrow * ALD + kof) * 2);
            }
            #pragma unroll
            for (int mt = 0; mt < 2; mt++)
                #pragma unroll
                for (int nt = 0; nt < 8; nt++)
                    mma16816(acc[mt][nt], af[mt], bf[nt]);
        }

        if (more) storeA(s + 1, (s + 1) & 1);
    }

    // ---- epilogue: +bias, float2 stores, optional per-channel stats ----
    #pragma unroll
    for (int nt = 0; nt < 8; nt++) {
        int col = wn * 64 + nt * 8 + 2 * t;
        float bv0 = bias[col], bv1 = bias[col + 1];
        float s0 = 0.f, q0 = 0.f, s1 = 0.f, q1 = 0.f;
        #pragma unroll
        for (int mt = 0; mt < 2; mt++) {
            int row = e0 + wm * 32 + mt * 16 + g;
            float a0 = acc[mt][nt][0] + bv0, a1 = acc[mt][nt][1] + bv1;
            float a2 = acc[mt][nt][2] + bv0, a3 = acc[mt][nt][3] + bv1;
            *(float2*)&Yout[((size_t)(b * E_ + row)) * ys + col] = make_float2(a0, a1);
            *(float2*)&Yout[((size_t)(b * E_ + row + 8)) * ys + col] = make_float2(a2, a3);
            s0 += a0 + a2;  q0 += a0 * a0 + a2 * a2;
            s1 += a1 + a3;  q1 += a1 * a1 + a3 * a3;
        }
        if (gsum) {
            // reduce over the 8 g-lanes (lane = 4g + t): xor masks 16,8,4
            #pragma unroll
            for (int m = 16; m >= 4; m >>= 1) {
                s0 += __shfl_xor_sync(0xffffffffu, s0, m);
                q0 += __shfl_xor_sync(0xffffffffu, q0, m);
                s1 += __shfl_xor_sync(0xffffffffu, s1, m);
                q1 += __shfl_xor_sync(0xffffffffu, q1, m);
            }
            if (g == 0) {
                atomicAdd(&gsum[b * 256 + col],     s0);
                atomicAdd(&gsum[b * 256 + col + 1], s1);
                atomicAdd(&gssq[b * 256 + col],     q0);
                atomicAdd(&gssq[b * 256 + col + 1], q1);
            }
        }
    }
}

// ---------------- finalize stats ----------------
__global__ void finalize_stats(const float* __restrict__ gsum, const float* __restrict__ gssq,
                               float* __restrict__ mean, float* __restrict__ rstd)
{
    int i = blockIdx.x * blockDim.x + threadIdx.x;
    if (i < B_ * 256) {
        float m = gsum[i] * (1.f / E_);
        float v = gssq[i] * (1.f / E_) - m * m;
        mean[i] = m;
        rstd[i] = rsqrtf(v + 1e-5f);
    }
}

// out = relu((Z-mean)*rstd [+ res]) in [B,E,256] layout
__global__ void apply_norm(const float* __restrict__ Z, const float* __restrict__ res,
                           const float* __restrict__ mean, const float* __restrict__ rstd,
                           float* __restrict__ out, int addres)
{
    size_t i = (size_t)blockIdx.x * blockDim.x + threadIdx.x;
    int b = (int)(i >> 20);
    int c = ((int)i & 63) * 4;
    float4 z = ((const float4*)Z)[i];
    int mi = b * 256 + c;
    float m0 = mean[mi], m1 = mean[mi + 1], m2 = mean[mi + 2], m3 = mean[mi + 3];
    float r0 = rstd[mi], r1 = rstd[mi + 1], r2 = rstd[mi + 2], r3 = rstd[mi + 3];
    float4 o;
    o.x = (z.x - m0) * r0;
    o.y = (z.y - m1) * r1;
    o.z = (z.z - m2) * r2;
    o.w = (z.w - m3) * r3;
    if (addres) {
        float4 rv = ((const float4*)res)[i];
        o.x += rv.x; o.y += rv.y; o.z += rv.z; o.w += rv.w;
    }
    o.x = fmaxf(o.x, 0.f);
    o.y = fmaxf(o.y, 0.f);
    o.z = fmaxf(o.z, 0.f);
    o.w = fmaxf(o.w, 0.f);
    ((float4*)out)[i] = o;
}

// final: relu((Z-mean)*rstd + res) with transposed store -> [B,256,E]
__global__ void apply_norm_t(const float* __restrict__ Z, const float* __restrict__ res,
                             const float* __restrict__ mean, const float* __restrict__ rstd,
                             float* __restrict__ out)
{
    __shared__ float tile[32][33];
    int b  = blockIdx.z;
    int e0 = blockIdx.x * 32, c0 = blockIdx.y * 32;
    int c  = c0 + threadIdx.x;
    float m = mean[b * 256 + c], r = rstd[b * 256 + c];
    #pragma unroll
    for (int i = threadIdx.y; i < 32; i += 8) {
        size_t idx = ((size_t)(b * E_ + e0 + i)) * 256 + c;
        float v = (Z[idx] - m) * r + res[idx];
        tile[i][threadIdx.x] = fmaxf(v, 0.f);
    }
    __syncthreads();
    float* op = out + ((size_t)(b * 256 + c0)) * E_ + e0;
    #pragma unroll
    for (int i = threadIdx.y; i < 32; i += 8)
        op[(size_t)i * E_ + threadIdx.x] = tile[threadIdx.x][i];
}

// ---------------- host ----------------
extern "C" void kernel_launch(void* const* d_in, const int* in_sizes, int n_in,
                              void* d_out, int out_size)
{
    const float* from_up   = (const float*)d_in[0];
    const float* from_down = (const float*)d_in[1];
    const int*   ei        = (const int*)  d_in[2];
    const float* W_up = (const float*)d_in[3];
    const float* b_up = (const float*)d_in[4];
    const float* W1   = (const float*)d_in[5];
    const float* b1   = (const float*)d_in[6];
    const float* W2a  = (const float*)d_in[7];
    const float* b2a  = (const float*)d_in[8];
    const float* W2b  = (const float*)d_in[9];
    const float* b2b  = (const float*)d_in[10];
    float* out = (float*)d_out;

    float *U, *X, *Z, *X1, *X2, *sum_, *ssq_, *mean_, *rstd_;
    __half *Wup, *W1r, *W2ar, *W2br;
    cudaGetSymbolAddress((void**)&U,    g_U);
    cudaGetSymbolAddress((void**)&X,    g_X);
    cudaGetSymbolAddress((void**)&Z,    g_Z);
    cudaGetSymbolAddress((void**)&X1,   g_X1);
    cudaGetSymbolAddress((void**)&X2,   g_X2);
    cudaGetSymbolAddress((void**)&Wup,  g_Wup);
    cudaGetSymbolAddress((void**)&W1r,  g_W1r);
    cudaGetSymbolAddress((void**)&W2ar, g_W2ar);
    cudaGetSymbolAddress((void**)&W2br, g_W2br);
    cudaGetSymbolAddress((void**)&sum_,  g_sum);
    cudaGetSymbolAddress((void**)&ssq_,  g_ssq);
    cudaGetSymbolAddress((void**)&mean_, g_mean);
    cudaGetSymbolAddress((void**)&rstd_, g_rstd);

    cudaFuncSetAttribute(gconv_mma, cudaFuncAttributeMaxDynamicSharedMemorySize, SMEM_BYTES);

    // weight images ([slab][o][k32], kind-paired, fp16)
    prep_w_img<<<(5 *  4 * 8192 + 255) / 256, 256>>>(W_up, Wup, 128);
    prep_w_img<<<(5 * 16 * 8192 + 255) / 256, 256>>>(W1,   W1r, 512);
    prep_w_img<<<(5 *  8 * 8192 + 255) / 256, 256>>>(W2a,  W2ar, 256);
    prep_w_img<<<(5 *  8 * 8192 + 255) / 256, 256>>>(W2b,  W2br, 256);

    dim3 tb(32, 8);
    trans_ce_ec<<<dim3(E_ / 32, 128 / 32, B_), tb>>>(from_up,   U, 128, 128, 0);
    trans_ce_ec<<<dim3(E_ / 32, 256 / 32, B_), tb>>>(from_down, X, 256, 512, 256);

    dim3 cg(E_ / 128, 1, B_);
    // conv1: writes concat cols 0..255 of X (no stats)
    gconv_mma<<<cg, 512, SMEM_BYTES>>>(U, 128, ei, Wup, b_up, X, 512, nullptr, nullptr);

    // conv2 with fused stats
    cudaMemsetAsync(sum_, 0, B_ * 256 * 4);
    cudaMemsetAsync(ssq_, 0, B_ * 256 * 4);
    gconv_mma<<<cg, 512, SMEM_BYTES>>>(X, 512, ei, W1r, b1, Z, 256, sum_, ssq_);
    finalize_stats<<<(B_ * 256 + 255) / 256, 256>>>(sum_, ssq_, mean_, rstd_);
    apply_norm<<<32768, 256>>>(Z, Z, mean_, rstd_, X1, 0);

    // residual block A with fused stats
    cudaMemsetAsync(sum_, 0, B_ * 256 * 4);
    cudaMemsetAsync(ssq_, 0, B_ * 256 * 4);
    gconv_mma<<<cg, 512, SMEM_BYTES>>>(X1, 256, ei, W2ar, b2a, Z, 256, sum_, ssq_);
    finalize_stats<<<(B_ * 256 + 255) / 256, 256>>>(sum_, ssq_, mean_, rstd_);
    apply_norm<<<32768, 256>>>(Z, X1, mean_, rstd_, X2, 1);

    // residual block B with fused stats; final norm writes transposed straight to out
    cudaMemsetAsync(sum_, 0, B_ * 256 * 4);
    cudaMemsetAsync(ssq_, 0, B_ * 256 * 4);
    gconv_mma<<<cg, 512, SMEM_BYTES>>>(X2, 256, ei, W2br, b2b, Z, 256, sum_, ssq_);
    finalize_stats<<<(B_ * 256 + 255) / 256, 256>>>(sum_, ssq_, mean_, rstd_);
    apply_norm_t<<<dim3(E_ / 32, 256 / 32, B_), tb>>>(Z, X2, mean_, rstd_, out);
}

// round 9
// speedup vs baseline: 4.2317x; 1.0010x over previous
#include <cuda_runtime.h>
#include <cuda_fp16.h>
#include <cuda_bf16.h>
#include <math.h>
#include <stdint.h>

#define B_ 8
#define E_ 16384
#define O_ 256

// ---------------- scratch (__device__ globals; no allocs allowed) ----------------
__device__ float g_U [(size_t)B_*E_*128];   // from_up, edge-major
__device__ float g_X [(size_t)B_*E_*512];   // concat(conv1, from_down), edge-major
__device__ float g_Z [(size_t)B_*E_*256];   // Z1 (conv2 out), later Z3 (conv4 out)
__device__ float g_Z2[(size_t)B_*E_*256];   // Z2 (conv3 out)
__device__ float g_X2[(size_t)B_*E_*256];   // block-A output (residual input for final)
__device__ __half g_Wup [5*128*256];
__device__ __half g_W1r [5*512*256];
__device__ __half g_W2ar[5*256*256];
__device__ __half g_W2br[5*256*256];
__device__ float g_sum  [B_*256];
__device__ float g_ssq  [B_*256];
__device__ float g_mean [B_*256];
__device__ float g_rstd [B_*256];
__device__ float g_mean2[B_*256];
__device__ float g_rstd2[B_*256];

__device__ __forceinline__ uint32_t smem_u32(const void* p) {
    uint32_t a;
    asm("{ .reg .u64 t; cvta.to.shared.u64 t, %1; cvt.u32.u64 %0, t; }" : "=r"(a) : "l"(p));
    return a;
}
#define CP_ASYNC16(dst, src) \
    asm volatile("cp.async.cg.shared.global [%0], [%1], 16;" :: "r"(dst), "l"(src))
#define CP_COMMIT() asm volatile("cp.async.commit_group;" ::: "memory")
#define CP_WAIT2()  asm volatile("cp.async.wait_group 2;" ::: "memory")
#define LDSM_X4(r0, r1, r2, r3, addr) \
    asm volatile("ldmatrix.sync.aligned.m8n8.x4.shared.b16 {%0,%1,%2,%3}, [%4];" \
        : "=r"(r0), "=r"(r1), "=r"(r2), "=r"(r3) : "r"(addr))

__device__ __forceinline__ void mma16816(float* d, const uint32_t* a, const uint32_t* b)
{
    asm volatile(
        "mma.sync.aligned.m16n8k16.row.col.f32.f16.f16.f32 "
        "{%0,%1,%2,%3}, {%4,%5,%6,%7}, {%8,%9}, {%0,%1,%2,%3};"
        : "+f"(d[0]), "+f"(d[1]), "+f"(d[2]), "+f"(d[3])
        : "r"(a[0]), "r"(a[1]), "r"(a[2]), "r"(a[3]), "r"(b[0]), "r"(b[1]));
}

__device__ __forceinline__ uint32_t h2u(float x, float y) {
    __half2 h = __floats2half2_rn(x, y);
    return *reinterpret_cast<uint32_t*>(&h);
}

// ---------------- slab map ----------------
// slab s (32 K-rows): cc = s/5, r = s%5
//  r=0: kind0 (center), channels [32cc, +32)
//  r=1: pair(1,3) chunk [32cc, +16)      rows 0-15 = n1+n3, rows 16-31 = |n1-n3|
//  r=2: pair(1,3) chunk [32cc+16, +16)
//  r=3: pair(2,4) chunk [32cc, +16)
//  r=4: pair(2,4) chunk [32cc+16, +16)

// ---------------- weight image prep: W[o,c,kk] -> [slab][o 0..255][k32], fp16 ----------------
__global__ void prep_w_img(const float* __restrict__ W, __half* __restrict__ Wimg, int C)
{
    int i = blockIdx.x * blockDim.x + threadIdx.x;
    int total = 5 * (C / 32) * 8192;
    if (i >= total) return;
    int slab   = i >> 13;
    int within = i & 8191;
    int o = within >> 5;
    int k = within & 31;
    int cc = slab / 5, r = slab % 5;
    int kind, c;
    if (r == 0) {
        kind = 0; c = 32 * cc + k;
    } else {
        int base  = (r <= 2) ? 1 : 2;
        int pairc = 32 * cc + ((r == 2 || r == 4) ? 16 : 0);
        if (k < 16) { kind = base;     c = pairc + k; }
        else        { kind = base + 2; c = pairc + k - 16; }
    }
    Wimg[i] = __float2half_rn(W[(o * C + c) * 5 + kind]);
}

// ---------------- transpose [B,C,E] -> [B,E,os] ----------------
__global__ void trans_ce_ec(const float* __restrict__ in, float* __restrict__ out,
                            int C, int os, int coff)
{
    __shared__ float tile[32][33];
    int b  = blockIdx.z;
    int e0 = blockIdx.x * 32, c0 = blockIdx.y * 32;
    const float* ip = in + ((size_t)b * C + c0) * E_ + e0;
    #pragma unroll
    for (int i = threadIdx.y; i < 32; i += 8)
        tile[i][threadIdx.x] = ip[(size_t)i * E_ + threadIdx.x];
    __syncthreads();
    float* op = out + ((size_t)(b * E_ + e0)) * os + coff + c0;
    #pragma unroll
    for (int i = threadIdx.y; i < 32; i += 8)
        op[(size_t)i * os + threadIdx.x] = tile[threadIdx.x][i];
}

// ---------------- fused gather + fp16 tensor-core GEMM (+ stats, + input-norm) ----------------
// Block: 128 edges x 256 outs, 512 threads (16 warps, 4x4: warp tile 32x64).
// A: 2-stage STS buffer. B: 4-stage cp.async ring (issue s+2, wait_group 2).
// NORM: gathered values v -> relu((v - mean[c]) * rstd[c]) on the fly (fp32, same
// formula as the old apply_norm -> bitwise-identical A-operands).
#define ALD 40                         // row stride in halves (80 B, 16B-aligned rows)
#define A_HALFS (128 * ALD)            // 5120
#define B_HALFS (256 * ALD)            // 10240
#define A_BYTES (A_HALFS * 2)          // 10240
#define B_BYTES (B_HALFS * 2)          // 20480
#define SMEM_BYTES (2 * A_BYTES + 4 * B_BYTES + 512 * 4)   // 104448

template <bool NORM>
__global__ __launch_bounds__(512)
void gconv_mma(const float* __restrict__ Xin, int C,
               const int* __restrict__ ei,
               const __half* __restrict__ Wimg,
               const float* __restrict__ bias,
               float* __restrict__ Yout, int ys,
               float* __restrict__ gsum, float* __restrict__ gssq,
               const float* __restrict__ nmean, const float* __restrict__ nrstd)
{
    extern __shared__ __half smh[];
    __half* smA = smh;                          // 2 stages
    __half* smB = smh + 2 * A_HALFS;            // 4 stages
    int*    aux_i = (int*)(smh + 2 * A_HALFS + 4 * B_HALFS);   // 512 ints
    float*  aux_f = (float*)aux_i;              // reused: [0..255]=mean, [256..511]=rstd
    const uint32_t sA_u32 = smem_u32(smA);
    const uint32_t sB_u32 = smem_u32(smB);

    const int tid  = threadIdx.x;
    const int wid  = tid >> 5;
    const int lane = tid & 31;
    const int g = lane >> 2;
    const int t = lane & 3;
    const int wm = wid >> 2;     // 0..3: 32-edge quarter
    const int wn = wid & 3;      // 0..3: 64-out quarter
    const int b  = blockIdx.z;
    const int e0 = blockIdx.x * 128;

    {
        const int* eip = ei + ((size_t)(b * E_) + e0) * 4;
        aux_i[tid] = (b * E_ + eip[tid]) * C;
    }
    __syncthreads();
    // neighbor bases for this thread's pair-edge (edge = tid>>2) into registers
    const int nb0 = aux_i[(tid >> 2) * 4 + 0];
    const int nb1 = aux_i[(tid >> 2) * 4 + 1];
    const int nb2 = aux_i[(tid >> 2) * 4 + 2];
    const int nb3 = aux_i[(tid >> 2) * 4 + 3];
    if (NORM) {
        __syncthreads();                         // all nb reads done before overwrite
        aux_f[tid] = (tid < 256) ? nmean[b * 256 + tid]
                                 : nrstd[b * 256 + (tid - 256)];
    }
    __syncthreads();

    const int x0base = (b * E_ + e0) * C;
    const int slabs  = 5 * (C / 32);

    float acc[2][8][4];
    #pragma unroll
    for (int mt = 0; mt < 2; mt++)
        #pragma unroll
        for (int nt = 0; nt < 8; nt++)
            #pragma unroll
            for (int rr = 0; rr < 4; rr++) acc[mt][nt][rr] = 0.f;

    float4 ga[2];

    auto norm4 = [&](float4 v, int cb) -> float4 {
        float4 m4 = *(float4*)&aux_f[cb];
        float4 r4 = *(float4*)&aux_f[256 + cb];
        v.x = fmaxf((v.x - m4.x) * r4.x, 0.f);
        v.y = fmaxf((v.y - m4.y) * r4.y, 0.f);
        v.z = fmaxf((v.z - m4.z) * r4.z, 0.f);
        v.w = fmaxf((v.w - m4.w) * r4.w, 0.f);
        return v;
    };

    auto gather = [&](int s) {
        int cc = s / 5, r = s % 5;
        if (r == 0) {
            int cbn = 32 * cc + (tid & 7) * 4;   // same for both j (512 % 8 == 0)
            #pragma unroll
            for (int j = 0; j < 2; j++) {
                int v = tid + j * 512;
                int edge = v >> 3, c4 = (v & 7) * 4;
                ga[j] = *(const float4*)&Xin[x0base + edge * C + 32 * cc + c4];
                if (NORM) ga[j] = norm4(ga[j], cbn);
            }
        } else {
            int na = (r <= 2) ? 0 : 1;
            int pc = 32 * cc + ((r == 2 || r == 4) ? 16 : 0);
            int c4 = (tid & 3) * 4;
            int c = pc + c4;
            int basep = (na == 0) ? nb0 : nb1;
            int baseq = (na == 0) ? nb2 : nb3;
            float4 p = *(const float4*)&Xin[basep + c];
            float4 q = *(const float4*)&Xin[baseq + c];
            if (NORM) { p = norm4(p, c); q = norm4(q, c); }
            ga[0] = make_float4(p.x + q.x, p.y + q.y, p.z + q.z, p.w + q.w);
            ga[1] = make_float4(fabsf(p.x - q.x), fabsf(p.y - q.y),
                                fabsf(p.z - q.z), fabsf(p.w - q.w));
        }
    };
    auto storeA = [&](int s, int buf) {
        __half* A = smA + buf * A_HALFS;
        int r = s % 5;
        if (r == 0) {
            #pragma unroll
            for (int j = 0; j < 2; j++) {
                int v = tid + j * 512;
                int edge = v >> 3, k = (v & 7) * 4;
                float4 a = ga[j];
                *(uint2*)&A[edge * ALD + k] = make_uint2(h2u(a.x, a.y), h2u(a.z, a.w));
            }
        } else {
            int edge = tid >> 2, k = (tid & 3) * 4;
            float4 sv = ga[0], dv = ga[1];
            *(uint2*)&A[edge * ALD + k]      = make_uint2(h2u(sv.x, sv.y), h2u(sv.z, sv.w));
            *(uint2*)&A[edge * ALD + 16 + k] = make_uint2(h2u(dv.x, dv.y), h2u(dv.z, dv.w));
        }
    };
    auto copyB = [&](int s, int stage) {
        const __half* src = Wimg + (size_t)s * 8192;
        uint32_t dstb = sB_u32 + stage * B_BYTES;
        #pragma unroll
        for (int j = 0; j < 2; j++) {
            int idx = tid + j * 512;
            int o = idx >> 2, seg = (idx & 3) * 8;   // halves
            CP_ASYNC16(dstb + (uint32_t)(o * ALD + seg) * 2, src + o * 32 + seg);
        }
    };

    // prologue
    copyB(0, 0);
    CP_COMMIT();
    copyB(1, 1);
    CP_COMMIT();
    gather(0);
    storeA(0, 0);

    for (int s = 0; s < slabs; s++) {
        bool more = (s + 1 < slabs);
        if (s + 2 < slabs) copyB(s + 2, (s + 2) & 3);
        CP_COMMIT();
        if (more) gather(s + 1);
        CP_WAIT2();
        __syncthreads();

        const uint32_t Abase = sA_u32 + (s & 1) * A_BYTES;
        const uint32_t Bbase = sB_u32 + (s & 3) * B_BYTES;
        #pragma unroll
        for (int ks = 0; ks < 2; ks++) {
            uint32_t af[2][4], bf[8][2];
            #pragma unroll
            for (int mt = 0; mt < 2; mt++) {
                int row = wm * 32 + mt * 16 + (lane & 15);
                int kof = ks * 16 + ((lane & 16) ? 8 : 0);
                LDSM_X4(af[mt][0], af[mt][1], af[mt][2], af[mt][3],
                        Abase + (uint32_t)(row * ALD + kof) * 2);
            }
            #pragma unroll
            for (int np = 0; np < 4; np++) {
                int nrow = wn * 64 + np * 16 + (lane & 7) + ((lane & 16) ? 8 : 0);
                int kof  = ks * 16 + ((lane & 8) ? 8 : 0);
                LDSM_X4(bf[2 * np][0], bf[2 * np][1], bf[2 * np + 1][0], bf[2 * np + 1][1],
                        Bbase + (uint32_t)(nrow * ALD + kof) * 2);
            }
            #pragma unroll
            for (int mt = 0; mt < 2; mt++)
                #pragma unroll
                for (int nt = 0; nt < 8; nt++)
                    mma16816(acc[mt][nt], af[mt], bf[nt]);
        }

        if (more) storeA(s + 1, (s + 1) & 1);
    }

    // ---- epilogue: +bias, float2 stores, optional per-channel stats ----
    #pragma unroll
    for (int nt = 0; nt < 8; nt++) {
        int col = wn * 64 + nt * 8 + 2 * t;
        float bv0 = bias[col], bv1 = bias[col + 1];
        float s0 = 0.f, q0 = 0.f, s1 = 0.f, q1 = 0.f;
        #pragma unroll
        for (int mt = 0; mt < 2; mt++) {
            int row = e0 + wm * 32 + mt * 16 + g;
            float a0 = acc[mt][nt][0] + bv0, a1 = acc[mt][nt][1] + bv1;
            float a2 = acc[mt][nt][2] + bv0, a3 = acc[mt][nt][3] + bv1;
            *(float2*)&Yout[((size_t)(b * E_ + row)) * ys + col] = make_float2(a0, a1);
            *(float2*)&Yout[((size_t)(b * E_ + row + 8)) * ys + col] = make_float2(a2, a3);
            s0 += a0 + a2;  q0 += a0 * a0 + a2 * a2;
            s1 += a1 + a3;  q1 += a1 * a1 + a3 * a3;
        }
        if (gsum) {
            #pragma unroll
            for (int m = 16; m >= 4; m >>= 1) {
                s0 += __shfl_xor_sync(0xffffffffu, s0, m);
                q0 += __shfl_xor_sync(0xffffffffu, q0, m);
                s1 += __shfl_xor_sync(0xffffffffu, s1, m);
                q1 += __shfl_xor_sync(0xffffffffu, q1, m);
            }
            if (g == 0) {
                atomicAdd(&gsum[b * 256 + col],     s0);
                atomicAdd(&gsum[b * 256 + col + 1], s1);
                atomicAdd(&gssq[b * 256 + col],     q0);
                atomicAdd(&gssq[b * 256 + col + 1], q1);
            }
        }
    }
}

// ---------------- finalize stats ----------------
__global__ void finalize_stats(const float* __restrict__ gsum, const float* __restrict__ gssq,
                               float* __restrict__ mean, float* __restrict__ rstd)
{
    int i = blockIdx.x * blockDim.x + threadIdx.x;
    if (i < B_ * 256) {
        float m = gsum[i] * (1.f / E_);
        float v = gssq[i] * (1.f / E_) - m * m;
        mean[i] = m;
        rstd[i] = rsqrtf(v + 1e-5f);
    }
}

// block-A combine: X2 = relu((Z2-m2)*r2 + relu((Z1-m1)*r1))
__global__ void apply_norm2(const float* __restrict__ Z2, const float* __restrict__ Z1,
                            const float* __restrict__ mean2, const float* __restrict__ rstd2,
                            const float* __restrict__ mean1, const float* __restrict__ rstd1,
                            float* __restrict__ out)
{
    size_t i = (size_t)blockIdx.x * blockDim.x + threadIdx.x;   // float4 index
    int b = (int)(i >> 20);
    int c = ((int)i & 63) * 4;
    float4 z2 = ((const float4*)Z2)[i];
    float4 z1 = ((const float4*)Z1)[i];
    int mi = b * 256 + c;
    float4 o;
    {
        float x1x = fmaxf((z1.x - mean1[mi])     * rstd1[mi],     0.f);
        float x1y = fmaxf((z1.y - mean1[mi + 1]) * rstd1[mi + 1], 0.f);
        float x1z = fmaxf((z1.z - mean1[mi + 2]) * rstd1[mi + 2], 0.f);
        float x1w = fmaxf((z1.w - mean1[mi + 3]) * rstd1[mi + 3], 0.f);
        o.x = fmaxf((z2.x - mean2[mi])     * rstd2[mi]     + x1x, 0.f);
        o.y = fmaxf((z2.y - mean2[mi + 1]) * rstd2[mi + 1] + x1y, 0.f);
        o.z = fmaxf((z2.z - mean2[mi + 2]) * rstd2[mi + 2] + x1z, 0.f);
        o.w = fmaxf((z2.w - mean2[mi + 3]) * rstd2[mi + 3] + x1w, 0.f);
    }
    ((float4*)out)[i] = o;
}

// final: relu((Z-mean)*rstd + res) with transposed store -> [B,256,E]
__global__ void apply_norm_t(const float* __restrict__ Z, const float* __restrict__ res,
                             const float* __restrict__ mean, const float* __restrict__ rstd,
                             float* __restrict__ out)
{
    __shared__ float tile[32][33];
    int b  = blockIdx.z;
    int e0 = blockIdx.x * 32, c0 = blockIdx.y * 32;
    int c  = c0 + threadIdx.x;
    float m = mean[b * 256 + c], r = rstd[b * 256 + c];
    #pragma unroll
    for (int i = threadIdx.y; i < 32; i += 8) {
        size_t idx = ((size_t)(b * E_ + e0 + i)) * 256 + c;
        float v = (Z[idx] - m) * r + res[idx];
        tile[i][threadIdx.x] = fmaxf(v, 0.f);
    }
    __syncthreads();
    float* op = out + ((size_t)(b * 256 + c0)) * E_ + e0;
    #pragma unroll
    for (int i = threadIdx.y; i < 32; i += 8)
        op[(size_t)i * E_ + threadIdx.x] = tile[threadIdx.x][i];
}

// ---------------- host ----------------
extern "C" void kernel_launch(void* const* d_in, const int* in_sizes, int n_in,
                              void* d_out, int out_size)
{
    const float* from_up   = (const float*)d_in[0];
    const float* from_down = (const float*)d_in[1];
    const int*   ei        = (const int*)  d_in[2];
    const float* W_up = (const float*)d_in[3];
    const float* b_up = (const float*)d_in[4];
    const float* W1   = (const float*)d_in[5];
    const float* b1   = (const float*)d_in[6];
    const float* W2a  = (const float*)d_in[7];
    const float* b2a  = (const float*)d_in[8];
    const float* W2b  = (const float*)d_in[9];
    const float* b2b  = (const float*)d_in[10];
    float* out = (float*)d_out;

    float *U, *X, *Z, *Z2, *X2;
    float *sum_, *ssq_, *mean1, *rstd1, *mean2, *rstd2;
    __half *Wup, *W1r, *W2ar, *W2br;
    cudaGetSymbolAddress((void**)&U,    g_U);
    cudaGetSymbolAddress((void**)&X,    g_X);
    cudaGetSymbolAddress((void**)&Z,    g_Z);
    cudaGetSymbolAddress((void**)&Z2,   g_Z2);
    cudaGetSymbolAddress((void**)&X2,   g_X2);
    cudaGetSymbolAddress((void**)&Wup,  g_Wup);
    cudaGetSymbolAddress((void**)&W1r,  g_W1r);
    cudaGetSymbolAddress((void**)&W2ar, g_W2ar);
    cudaGetSymbolAddress((void**)&W2br, g_W2br);
    cudaGetSymbolAddress((void**)&sum_,  g_sum);
    cudaGetSymbolAddress((void**)&ssq_,  g_ssq);
    cudaGetSymbolAddress((void**)&mean1, g_mean);
    cudaGetSymbolAddress((void**)&rstd1, g_rstd);
    cudaGetSymbolAddress((void**)&mean2, g_mean2);
    cudaGetSymbolAddress((void**)&rstd2, g_rstd2);

    cudaFuncSetAttribute(gconv_mma<false>, cudaFuncAttributeMaxDynamicSharedMemorySize, SMEM_BYTES);
    cudaFuncSetAttribute(gconv_mma<true>,  cudaFuncAttributeMaxDynamicSharedMemorySize, SMEM_BYTES);

    // weight images ([slab][o][k32], kind-paired, fp16)
    prep_w_img<<<(5 *  4 * 8192 + 255) / 256, 256>>>(W_up, Wup, 128);
    prep_w_img<<<(5 * 16 * 8192 + 255) / 256, 256>>>(W1,   W1r, 512);
    prep_w_img<<<(5 *  8 * 8192 + 255) / 256, 256>>>(W2a,  W2ar, 256);
    prep_w_img<<<(5 *  8 * 8192 + 255) / 256, 256>>>(W2b,  W2br, 256);

    dim3 tb(32, 8);
    trans_ce_ec<<<dim3(E_ / 32, 128 / 32, B_), tb>>>(from_up,   U, 128, 128, 0);
    trans_ce_ec<<<dim3(E_ / 32, 256 / 32, B_), tb>>>(from_down, X, 256, 512, 256);

    dim3 cg(E_ / 128, 1, B_);
    // conv1: writes concat cols 0..255 of X (no stats, no norm)
    gconv_mma<false><<<cg, 512, SMEM_BYTES>>>(U, 128, ei, Wup, b_up, X, 512,
                                              nullptr, nullptr, nullptr, nullptr);

    // conv2 -> Z1, fused stats
    cudaMemsetAsync(sum_, 0, B_ * 256 * 4);
    cudaMemsetAsync(ssq_, 0, B_ * 256 * 4);
    gconv_mma<false><<<cg, 512, SMEM_BYTES>>>(X, 512, ei, W1r, b1, Z, 256,
                                              sum_, ssq_, nullptr, nullptr);
    finalize_stats<<<(B_ * 256 + 255) / 256, 256>>>(sum_, ssq_, mean1, rstd1);

    // conv3: gathers relu(norm(Z1)) on the fly -> Z2, fused stats (X1 never materialized)
    cudaMemsetAsync(sum_, 0, B_ * 256 * 4);
    cudaMemsetAsync(ssq_, 0, B_ * 256 * 4);
    gconv_mma<true><<<cg, 512, SMEM_BYTES>>>(Z, 256, ei, W2ar, b2a, Z2, 256,
                                             sum_, ssq_, mean1, rstd1);
    finalize_stats<<<(B_ * 256 + 255) / 256, 256>>>(sum_, ssq_, mean2, rstd2);

    // block-A combine: X2 = relu(norm2(Z2) + relu(norm1(Z1)))
    apply_norm2<<<32768, 256>>>(Z2, Z, mean2, rstd2, mean1, rstd1, X2);

    // conv4: input X2 -> Z3 (reuse g_Z; Z1 dead), fused stats
    cudaMemsetAsync(sum_, 0, B_ * 256 * 4);
    cudaMemsetAsync(ssq_, 0, B_ * 256 * 4);
    gconv_mma<false><<<cg, 512, SMEM_BYTES>>>(X2, 256, ei, W2br, b2b, Z, 256,
                                              sum_, ssq_, nullptr, nullptr);
    finalize_stats<<<(B_ * 256 + 255) / 256, 256>>>(sum_, ssq_, mean1, rstd1);

    // final: relu(norm(Z3) + X2), transposed straight to out
    apply_norm_t<<<dim3(E_ / 32, 256 / 32, B_), tb>>>(Z, X2, mean1, rstd1, out);
}

// round 10
// speedup vs baseline: 4.2687x; 1.0087x over previous
#include <cuda_runtime.h>
#include <cuda_fp16.h>
#include <cuda_bf16.h>
#include <math.h>
#include <stdint.h>

#define B_ 8
#define E_ 16384
#define O_ 256

// ---------------- scratch (__device__ globals; no allocs allowed) ----------------
__device__ float g_U [(size_t)B_*E_*128];   // from_up, edge-major
__device__ float g_X [(size_t)B_*E_*512];   // concat(conv1, from_down), edge-major
__device__ float g_Z [(size_t)B_*E_*256];   // Z1 (conv2 out), later Z3 (conv4 out)
__device__ float g_Z2[(size_t)B_*E_*256];   // Z2 (conv3 out)
__device__ float g_X2[(size_t)B_*E_*256];   // block-A output (residual input for final)
__device__ __half g_Wup [5*128*256];
__device__ __half g_W1r [5*512*256];
__device__ __half g_W2ar[5*256*256];
__device__ __half g_W2br[5*256*256];
// stats: [0]=sum1 [2048]=ssq1 [4096]=sum2 [6144]=ssq2 [8192]=sum3 [10240]=ssq3
__device__ float g_stats[6*2048];
__device__ float g_mean [B_*256];
__device__ float g_rstd [B_*256];
__device__ float g_mean2[B_*256];
__device__ float g_rstd2[B_*256];

__device__ __forceinline__ uint32_t smem_u32(const void* p) {
    uint32_t a;
    asm("{ .reg .u64 t; cvta.to.shared.u64 t, %1; cvt.u32.u64 %0, t; }" : "=r"(a) : "l"(p));
    return a;
}
#define CP_ASYNC16(dst, src) \
    asm volatile("cp.async.cg.shared.global [%0], [%1], 16;" :: "r"(dst), "l"(src))
#define CP_COMMIT() asm volatile("cp.async.commit_group;" ::: "memory")
#define CP_WAIT2()  asm volatile("cp.async.wait_group 2;" ::: "memory")
#define LDSM_X4(r0, r1, r2, r3, addr) \
    asm volatile("ldmatrix.sync.aligned.m8n8.x4.shared.b16 {%0,%1,%2,%3}, [%4];" \
        : "=r"(r0), "=r"(r1), "=r"(r2), "=r"(r3) : "r"(addr))

__device__ __forceinline__ void mma16816(float* d, const uint32_t* a, const uint32_t* b)
{
    asm volatile(
        "mma.sync.aligned.m16n8k16.row.col.f32.f16.f16.f32 "
        "{%0,%1,%2,%3}, {%4,%5,%6,%7}, {%8,%9}, {%0,%1,%2,%3};"
        : "+f"(d[0]), "+f"(d[1]), "+f"(d[2]), "+f"(d[3])
        : "r"(a[0]), "r"(a[1]), "r"(a[2]), "r"(a[3]), "r"(b[0]), "r"(b[1]));
}

__device__ __forceinline__ uint32_t h2u(float x, float y) {
    __half2 h = __floats2half2_rn(x, y);
    return *reinterpret_cast<uint32_t*>(&h);
}

// ---------------- slab map ----------------
// slab s (32 K-rows): cc = s/5, r = s%5
//  r=0: kind0 (center), channels [32cc, +32)
//  r=1: pair(1,3) chunk [32cc, +16)      rows 0-15 = n1+n3, rows 16-31 = |n1-n3|
//  r=2: pair(1,3) chunk [32cc+16, +16)
//  r=3: pair(2,4) chunk [32cc, +16)
//  r=4: pair(2,4) chunk [32cc+16, +16)

// ---------------- merged weight image prep (all 4 tensors in one kernel) ----------------
// slabs: [0,20)=W_up(C=128) [20,100)=W1(C=512) [100,140)=W2a(C=256) [140,180)=W2b(C=256)
__global__ void prep_w_all(const float* __restrict__ W_up, const float* __restrict__ W1,
                           const float* __restrict__ W2a, const float* __restrict__ W2b,
                           __half* __restrict__ Wup, __half* __restrict__ W1r,
                           __half* __restrict__ W2ar, __half* __restrict__ W2br)
{
    int i = blockIdx.x * blockDim.x + threadIdx.x;   // < 180*8192
    int s = i >> 13;
    int within = i & 8191;
    const float* W; __half* O; int C;
    if (s < 20)       { W = W_up; O = Wup;  C = 128; }
    else if (s < 100) { W = W1;   O = W1r;  C = 512; s -= 20; }
    else if (s < 140) { W = W2a;  O = W2ar; C = 256; s -= 100; }
    else              { W = W2b;  O = W2br; C = 256; s -= 140; }
    int o = within >> 5;
    int k = within & 31;
    int cc = s / 5, r = s % 5;
    int kind, c;
    if (r == 0) {
        kind = 0; c = 32 * cc + k;
    } else {
        int base  = (r <= 2) ? 1 : 2;
        int pairc = 32 * cc + ((r == 2 || r == 4) ? 16 : 0);
        if (k < 16) { kind = base;     c = pairc + k; }
        else        { kind = base + 2; c = pairc + k - 16; }
    }
    O[(size_t)s * 8192 + within] = __float2half_rn(W[(o * C + c) * 5 + kind]);
}

// ---------------- merged transpose: from_up -> U, from_down -> X cols 256.. ----------------
// grid.y in [0,12): y<4 -> from_up c-tile y; else from_down c-tile y-4
__global__ void trans_both(const float* __restrict__ from_up, const float* __restrict__ from_down,
                           float* __restrict__ U, float* __restrict__ X)
{
    __shared__ float tile[32][33];
    int b  = blockIdx.z;
    int e0 = blockIdx.x * 32;
    const float* in; float* out; int C, os, coff, c0;
    if (blockIdx.y < 4) { in = from_up;   out = U; C = 128; os = 128; coff = 0;   c0 = blockIdx.y * 32; }
    else                { in = from_down; out = X; C = 256; os = 512; coff = 256; c0 = (blockIdx.y - 4) * 32; }
    const float* ip = in + ((size_t)b * C + c0) * E_ + e0;
    #pragma unroll
    for (int i = threadIdx.y; i < 32; i += 8)
        tile[i][threadIdx.x] = ip[(size_t)i * E_ + threadIdx.x];
    __syncthreads();
    float* op = out + ((size_t)(b * E_ + e0)) * os + coff + c0;
    #pragma unroll
    for (int i = threadIdx.y; i < 32; i += 8)
        op[(size_t)i * os + threadIdx.x] = tile[threadIdx.x][i];
}

// ---------------- fused gather + fp16 tensor-core GEMM (+ stats, + input-norm) ----------------
#define ALD 40                         // row stride in halves (80 B, 16B-aligned rows)
#define A_HALFS (128 * ALD)            // 5120
#define B_HALFS (256 * ALD)            // 10240
#define A_BYTES (A_HALFS * 2)          // 10240
#define B_BYTES (B_HALFS * 2)          // 20480
#define SMEM_BYTES (2 * A_BYTES + 4 * B_BYTES + 512 * 4)   // 104448

template <bool NORM>
__global__ __launch_bounds__(512)
void gconv_mma(const float* __restrict__ Xin, int C,
               const int* __restrict__ ei,
               const __half* __restrict__ Wimg,
               const float* __restrict__ bias,
               float* __restrict__ Yout, int ys,
               float* __restrict__ gsum, float* __restrict__ gssq,
               const float* __restrict__ nmean, const float* __restrict__ nrstd,
               float* __restrict__ zbuf)
{
    extern __shared__ __half smh[];
    __half* smA = smh;                          // 2 stages
    __half* smB = smh + 2 * A_HALFS;            // 4 stages
    int*    aux_i = (int*)(smh + 2 * A_HALFS + 4 * B_HALFS);   // 512 ints
    float*  aux_f = (float*)aux_i;              // reused: [0..255]=mean, [256..511]=rstd
    const uint32_t sA_u32 = smem_u32(smA);
    const uint32_t sB_u32 = smem_u32(smB);

    const int tid  = threadIdx.x;
    const int wid  = tid >> 5;
    const int lane = tid & 31;
    const int g = lane >> 2;
    const int t = lane & 3;
    const int wm = wid >> 2;     // 0..3: 32-edge quarter
    const int wn = wid & 3;      // 0..3: 64-out quarter
    const int b  = blockIdx.z;
    const int e0 = blockIdx.x * 128;

    // one-time zero of the stats array (conv1 only): first 6 blocks of z==0
    if (zbuf && b == 0 && blockIdx.x < 6) {
        float* zp = zbuf + blockIdx.x * 2048;
        *(float4*)&zp[tid * 4] = make_float4(0.f, 0.f, 0.f, 0.f);
    }

    {
        const int* eip = ei + ((size_t)(b * E_) + e0) * 4;
        aux_i[tid] = (b * E_ + eip[tid]) * C;
    }
    __syncthreads();
    const int nb0 = aux_i[(tid >> 2) * 4 + 0];
    const int nb1 = aux_i[(tid >> 2) * 4 + 1];
    const int nb2 = aux_i[(tid >> 2) * 4 + 2];
    const int nb3 = aux_i[(tid >> 2) * 4 + 3];
    if (NORM) {
        __syncthreads();
        aux_f[tid] = (tid < 256) ? nmean[b * 256 + tid]
                                 : nrstd[b * 256 + (tid - 256)];
    }
    __syncthreads();

    const int x0base = (b * E_ + e0) * C;
    const int slabs  = 5 * (C / 32);

    float acc[2][8][4];
    #pragma unroll
    for (int mt = 0; mt < 2; mt++)
        #pragma unroll
        for (int nt = 0; nt < 8; nt++)
            #pragma unroll
            for (int rr = 0; rr < 4; rr++) acc[mt][nt][rr] = 0.f;

    float4 ga[2];

    auto norm4 = [&](float4 v, int cb) -> float4 {
        float4 m4 = *(float4*)&aux_f[cb];
        float4 r4 = *(float4*)&aux_f[256 + cb];
        v.x = fmaxf((v.x - m4.x) * r4.x, 0.f);
        v.y = fmaxf((v.y - m4.y) * r4.y, 0.f);
        v.z = fmaxf((v.z - m4.z) * r4.z, 0.f);
        v.w = fmaxf((v.w - m4.w) * r4.w, 0.f);
        return v;
    };

    auto gather = [&](int s) {
        int cc = s / 5, r = s % 5;
        if (r == 0) {
            int cbn = 32 * cc + (tid & 7) * 4;
            #pragma unroll
            for (int j = 0; j < 2; j++) {
                int v = tid + j * 512;
                int edge = v >> 3, c4 = (v & 7) * 4;
                ga[j] = *(const float4*)&Xin[x0base + edge * C + 32 * cc + c4];
                if (NORM) ga[j] = norm4(ga[j], cbn);
            }
        } else {
            int na = (r <= 2) ? 0 : 1;
            int pc = 32 * cc + ((r == 2 || r == 4) ? 16 : 0);
            int c4 = (tid & 3) * 4;
            int c = pc + c4;
            int basep = (na == 0) ? nb0 : nb1;
            int baseq = (na == 0) ? nb2 : nb3;
            float4 p = *(const float4*)&Xin[basep + c];
            float4 q = *(const float4*)&Xin[baseq + c];
            if (NORM) { p = norm4(p, c); q = norm4(q, c); }
            ga[0] = make_float4(p.x + q.x, p.y + q.y, p.z + q.z, p.w + q.w);
            ga[1] = make_float4(fabsf(p.x - q.x), fabsf(p.y - q.y),
                                fabsf(p.z - q.z), fabsf(p.w - q.w));
        }
    };
    auto storeA = [&](int s, int buf) {
        __half* A = smA + buf * A_HALFS;
        int r = s % 5;
        if (r == 0) {
            #pragma unroll
            for (int j = 0; j < 2; j++) {
                int v = tid + j * 512;
                int edge = v >> 3, k = (v & 7) * 4;
                float4 a = ga[j];
                *(uint2*)&A[edge * ALD + k] = make_uint2(h2u(a.x, a.y), h2u(a.z, a.w));
            }
        } else {
            int edge = tid >> 2, k = (tid & 3) * 4;
            float4 sv = ga[0], dv = ga[1];
            *(uint2*)&A[edge * ALD + k]      = make_uint2(h2u(sv.x, sv.y), h2u(sv.z, sv.w));
            *(uint2*)&A[edge * ALD + 16 + k] = make_uint2(h2u(dv.x, dv.y), h2u(dv.z, dv.w));
        }
    };
    auto copyB = [&](int s, int stage) {
        const __half* src = Wimg + (size_t)s * 8192;
        uint32_t dstb = sB_u32 + stage * B_BYTES;
        #pragma unroll
        for (int j = 0; j < 2; j++) {
            int idx = tid + j * 512;
            int o = idx >> 2, seg = (idx & 3) * 8;   // halves
            CP_ASYNC16(dstb + (uint32_t)(o * ALD + seg) * 2, src + o * 32 + seg);
        }
    };

    // prologue
    copyB(0, 0);
    CP_COMMIT();
    copyB(1, 1);
    CP_COMMIT();
    gather(0);
    storeA(0, 0);

    for (int s = 0; s < slabs; s++) {
        bool more = (s + 1 < slabs);
        if (s + 2 < slabs) copyB(s + 2, (s + 2) & 3);
        CP_COMMIT();
        if (more) gather(s + 1);
        CP_WAIT2();
        __syncthreads();

        const uint32_t Abase = sA_u32 + (s & 1) * A_BYTES;
        const uint32_t Bbase = sB_u32 + (s & 3) * B_BYTES;
        #pragma unroll
        for (int ks = 0; ks < 2; ks++) {
            uint32_t af[2][4], bf[8][2];
            #pragma unroll
            for (int mt = 0; mt < 2; mt++) {
                int row = wm * 32 + mt * 16 + (lane & 15);
                int kof = ks * 16 + ((lane & 16) ? 8 : 0);
                LDSM_X4(af[mt][0], af[mt][1], af[mt][2], af[mt][3],
                        Abase + (uint32_t)(row * ALD + kof) * 2);
            }
            #pragma unroll
            for (int np = 0; np < 4; np++) {
                int nrow = wn * 64 + np * 16 + (lane & 7) + ((lane & 16) ? 8 : 0);
                int kof  = ks * 16 + ((lane & 8) ? 8 : 0);
                LDSM_X4(bf[2 * np][0], bf[2 * np][1], bf[2 * np + 1][0], bf[2 * np + 1][1],
                        Bbase + (uint32_t)(nrow * ALD + kof) * 2);
            }
            #pragma unroll
            for (int mt = 0; mt < 2; mt++)
                #pragma unroll
                for (int nt = 0; nt < 8; nt++)
                    mma16816(acc[mt][nt], af[mt], bf[nt]);
        }

        if (more) storeA(s + 1, (s + 1) & 1);
    }

    // ---- epilogue: +bias, float2 stores, optional per-channel stats ----
    #pragma unroll
    for (int nt = 0; nt < 8; nt++) {
        int col = wn * 64 + nt * 8 + 2 * t;
        float bv0 = bias[col], bv1 = bias[col + 1];
        float s0 = 0.f, q0 = 0.f, s1 = 0.f, q1 = 0.f;
        #pragma unroll
        for (int mt = 0; mt < 2; mt++) {
            int row = e0 + wm * 32 + mt * 16 + g;
            float a0 = acc[mt][nt][0] + bv0, a1 = acc[mt][nt][1] + bv1;
            float a2 = acc[mt][nt][2] + bv0, a3 = acc[mt][nt][3] + bv1;
            *(float2*)&Yout[((size_t)(b * E_ + row)) * ys + col] = make_float2(a0, a1);
            *(float2*)&Yout[((size_t)(b * E_ + row + 8)) * ys + col] = make_float2(a2, a3);
            s0 += a0 + a2;  q0 += a0 * a0 + a2 * a2;
            s1 += a1 + a3;  q1 += a1 * a1 + a3 * a3;
        }
        if (gsum) {
            #pragma unroll
            for (int m = 16; m >= 4; m >>= 1) {
                s0 += __shfl_xor_sync(0xffffffffu, s0, m);
                q0 += __shfl_xor_sync(0xffffffffu, q0, m);
                s1 += __shfl_xor_sync(0xffffffffu, s1, m);
                q1 += __shfl_xor_sync(0xffffffffu, q1, m);
            }
            if (g == 0) {
                atomicAdd(&gsum[b * 256 + col],     s0);
                atomicAdd(&gsum[b * 256 + col + 1], s1);
                atomicAdd(&gssq[b * 256 + col],     q0);
                atomicAdd(&gssq[b * 256 + col + 1], q1);
            }
        }
    }
}

// ---------------- finalize stats ----------------
__global__ void finalize_stats(const float* __restrict__ gsum, const float* __restrict__ gssq,
                               float* __restrict__ mean, float* __restrict__ rstd)
{
    int i = blockIdx.x * blockDim.x + threadIdx.x;
    if (i < B_ * 256) {
        float m = gsum[i] * (1.f / E_);
        float v = gssq[i] * (1.f / E_) - m * m;
        mean[i] = m;
        rstd[i] = rsqrtf(v + 1e-5f);
    }
}

// block-A combine: X2 = relu((Z2-m2)*r2 + relu((Z1-m1)*r1))
__global__ void apply_norm2(const float* __restrict__ Z2, const float* __restrict__ Z1,
                            const float* __restrict__ mean2, const float* __restrict__ rstd2,
                            const float* __restrict__ mean1, const float* __restrict__ rstd1,
                            float* __restrict__ out)
{
    size_t i = (size_t)blockIdx.x * blockDim.x + threadIdx.x;   // float4 index
    int b = (int)(i >> 20);
    int c = ((int)i & 63) * 4;
    float4 z2 = ((const float4*)Z2)[i];
    float4 z1 = ((const float4*)Z1)[i];
    int mi = b * 256 + c;
    float4 o;
    {
        float x1x = fmaxf((z1.x - mean1[mi])     * rstd1[mi],     0.f);
        float x1y = fmaxf((z1.y - mean1[mi + 1]) * rstd1[mi + 1], 0.f);
        float x1z = fmaxf((z1.z - mean1[mi + 2]) * rstd1[mi + 2], 0.f);
        float x1w = fmaxf((z1.w - mean1[mi + 3]) * rstd1[mi + 3], 0.f);
        o.x = fmaxf((z2.x - mean2[mi])     * rstd2[mi]     + x1x, 0.f);
        o.y = fmaxf((z2.y - mean2[mi + 1]) * rstd2[mi + 1] + x1y, 0.f);
        o.z = fmaxf((z2.z - mean2[mi + 2]) * rstd2[mi + 2] + x1z, 0.f);
        o.w = fmaxf((z2.w - mean2[mi + 3]) * rstd2[mi + 3] + x1w, 0.f);
    }
    ((float4*)out)[i] = o;
}

// final: relu((Z-mean)*rstd + res) with transposed store -> [B,256,E]
__global__ void apply_norm_t(const float* __restrict__ Z, const float* __restrict__ res,
                             const float* __restrict__ mean, const float* __restrict__ rstd,
                             float* __restrict__ out)
{
    __shared__ float tile[32][33];
    int b  = blockIdx.z;
    int e0 = blockIdx.x * 32, c0 = blockIdx.y * 32;
    int c  = c0 + threadIdx.x;
    float m = mean[b * 256 + c], r = rstd[b * 256 + c];
    #pragma unroll
    for (int i = threadIdx.y; i < 32; i += 8) {
        size_t idx = ((size_t)(b * E_ + e0 + i)) * 256 + c;
        float v = (Z[idx] - m) * r + res[idx];
        tile[i][threadIdx.x] = fmaxf(v, 0.f);
    }
    __syncthreads();
    float* op = out + ((size_t)(b * 256 + c0)) * E_ + e0;
    #pragma unroll
    for (int i = threadIdx.y; i < 32; i += 8)
        op[(size_t)i * E_ + threadIdx.x] = tile[threadIdx.x][i];
}

// ---------------- host ----------------
extern "C" void kernel_launch(void* const* d_in, const int* in_sizes, int n_in,
                              void* d_out, int out_size)
{
    const float* from_up   = (const float*)d_in[0];
    const float* from_down = (const float*)d_in[1];
    const int*   ei        = (const int*)  d_in[2];
    const float* W_up = (const float*)d_in[3];
    const float* b_up = (const float*)d_in[4];
    const float* W1   = (const float*)d_in[5];
    const float* b1   = (const float*)d_in[6];
    const float* W2a  = (const float*)d_in[7];
    const float* b2a  = (const float*)d_in[8];
    const float* W2b  = (const float*)d_in[9];
    const float* b2b  = (const float*)d_in[10];
    float* out = (float*)d_out;

    float *U, *X, *Z, *Z2, *X2, *stats, *mean1, *rstd1, *mean2, *rstd2;
    __half *Wup, *W1r, *W2ar, *W2br;
    cudaGetSymbolAddress((void**)&U,    g_U);
    cudaGetSymbolAddress((void**)&X,    g_X);
    cudaGetSymbolAddress((void**)&Z,    g_Z);
    cudaGetSymbolAddress((void**)&Z2,   g_Z2);
    cudaGetSymbolAddress((void**)&X2,   g_X2);
    cudaGetSymbolAddress((void**)&Wup,  g_Wup);
    cudaGetSymbolAddress((void**)&W1r,  g_W1r);
    cudaGetSymbolAddress((void**)&W2ar, g_W2ar);
    cudaGetSymbolAddress((void**)&W2br, g_W2br);
    cudaGetSymbolAddress((void**)&stats, g_stats);
    cudaGetSymbolAddress((void**)&mean1, g_mean);
    cudaGetSymbolAddress((void**)&rstd1, g_rstd);
    cudaGetSymbolAddress((void**)&mean2, g_mean2);
    cudaGetSymbolAddress((void**)&rstd2, g_rstd2);

    float* sum1 = stats;           float* ssq1 = stats + 2048;
    float* sum2 = stats + 4096;    float* ssq2 = stats + 6144;
    float* sum3 = stats + 8192;    float* ssq3 = stats + 10240;

    cudaFuncSetAttribute(gconv_mma<false>, cudaFuncAttributeMaxDynamicSharedMemorySize, SMEM_BYTES);
    cudaFuncSetAttribute(gconv_mma<true>,  cudaFuncAttributeMaxDynamicSharedMemorySize, SMEM_BYTES);

    // (1) merged weight-image prep
    prep_w_all<<<(180 * 8192) / 256, 256>>>(W_up, W1, W2a, W2b, Wup, W1r, W2ar, W2br);

    // (2) merged input transposes
    trans_both<<<dim3(E_ / 32, 12, B_), dim3(32, 8)>>>(from_up, from_down, U, X);

    dim3 cg(E_ / 128, 1, B_);
    // (3) conv1 -> X cols 0..255; also zeroes the whole stats array
    gconv_mma<false><<<cg, 512, SMEM_BYTES>>>(U, 128, ei, Wup, b_up, X, 512,
                                              nullptr, nullptr, nullptr, nullptr, stats);

    // (4) conv2 -> Z1, fused stats  [ncu capture slot target]
    gconv_mma<false><<<cg, 512, SMEM_BYTES>>>(X, 512, ei, W1r, b1, Z, 256,
                                              sum1, ssq1, nullptr, nullptr, nullptr);
    finalize_stats<<<(B_ * 256 + 255) / 256, 256>>>(sum1, ssq1, mean1, rstd1);

    // conv3: gathers relu(norm1(Z1)) on the fly -> Z2, fused stats
    gconv_mma<true><<<cg, 512, SMEM_BYTES>>>(Z, 256, ei, W2ar, b2a, Z2, 256,
                                             sum2, ssq2, mean1, rstd1, nullptr);
    finalize_stats<<<(B_ * 256 + 255) / 256, 256>>>(sum2, ssq2, mean2, rstd2);

    // block-A combine: X2 = relu(norm2(Z2) + relu(norm1(Z1)))
    apply_norm2<<<32768, 256>>>(Z2, Z, mean2, rstd2, mean1, rstd1, X2);

    // conv4: X2 -> Z3 (reuse g_Z), fused stats
    gconv_mma<false><<<cg, 512, SMEM_BYTES>>>(X2, 256, ei, W2br, b2b, Z, 256,
                                              sum3, ssq3, nullptr, nullptr, nullptr);
    finalize_stats<<<(B_ * 256 + 255) / 256, 256>>>(sum3, ssq3, mean1, rstd1);

    // final: relu(norm(Z3) + X2), transposed straight to out
    apply_norm_t<<<dim3(E_ / 32, 256 / 32, B_), dim3(32, 8)>>>(Z, X2, mean1, rstd1, out);
}

// round 11
// speedup vs baseline: 4.7226x; 1.1063x over previous
#include <cuda_runtime.h>
#include <cuda_fp16.h>
#include <cuda_bf16.h>
#include <math.h>
#include <stdint.h>

#define B_ 8
#define E_ 16384
#define O_ 256

// ---------------- scratch (__device__ globals; no allocs allowed) ----------------
__device__ float g_U [(size_t)B_*E_*128];   // from_up, edge-major
__device__ float g_X [(size_t)B_*E_*512];   // concat(conv1, from_down), edge-major
__device__ float g_Z [(size_t)B_*E_*256];   // Z1 (conv2 out), later Z3 (conv4 out)
__device__ float g_Z2[(size_t)B_*E_*256];   // Z2 (conv3 out)
__device__ float g_X2[(size_t)B_*E_*256];   // block-A output (residual input for final)
__device__ __half g_Wup [5*128*256];
__device__ __half g_W1r [5*512*256];
__device__ __half g_W2ar[5*256*256];
__device__ __half g_W2br[5*256*256];
// stats: [0]=sum1 [2048]=ssq1 [4096]=sum2 [6144]=ssq2 [8192]=sum3 [10240]=ssq3
__device__ float g_stats[6*2048];
__device__ float g_mean [B_*256];
__device__ float g_rstd [B_*256];
__device__ float g_mean2[B_*256];
__device__ float g_rstd2[B_*256];

__device__ __forceinline__ uint32_t smem_u32(const void* p) {
    uint32_t a;
    asm("{ .reg .u64 t; cvta.to.shared.u64 t, %1; cvt.u32.u64 %0, t; }" : "=r"(a) : "l"(p));
    return a;
}
#define CP_ASYNC16(dst, src) \
    asm volatile("cp.async.cg.shared.global [%0], [%1], 16;" :: "r"(dst), "l"(src))
#define CP_COMMIT() asm volatile("cp.async.commit_group;" ::: "memory")
#define CP_WAIT1()  asm volatile("cp.async.wait_group 1;" ::: "memory")
#define LDSM_X4(r0, r1, r2, r3, addr) \
    asm volatile("ldmatrix.sync.aligned.m8n8.x4.shared.b16 {%0,%1,%2,%3}, [%4];" \
        : "=r"(r0), "=r"(r1), "=r"(r2), "=r"(r3) : "r"(addr))

__device__ __forceinline__ void mma16816(float* d, const uint32_t* a, const uint32_t* b)
{
    asm volatile(
        "mma.sync.aligned.m16n8k16.row.col.f32.f16.f16.f32 "
        "{%0,%1,%2,%3}, {%4,%5,%6,%7}, {%8,%9}, {%0,%1,%2,%3};"
        : "+f"(d[0]), "+f"(d[1]), "+f"(d[2]), "+f"(d[3])
        : "r"(a[0]), "r"(a[1]), "r"(a[2]), "r"(a[3]), "r"(b[0]), "r"(b[1]));
}

__device__ __forceinline__ uint32_t h2u(float x, float y) {
    __half2 h = __floats2half2_rn(x, y);
    return *reinterpret_cast<uint32_t*>(&h);
}

// ---------------- slab map ----------------
// slab s (32 K-rows): cc = s/5, r = s%5
//  r=0: kind0 (center), channels [32cc, +32)
//  r=1: pair(1,3) chunk [32cc, +16)      rows 0-15 = n1+n3, rows 16-31 = |n1-n3|
//  r=2: pair(1,3) chunk [32cc+16, +16)
//  r=3: pair(2,4) chunk [32cc, +16)
//  r=4: pair(2,4) chunk [32cc+16, +16)

// ---------------- merged weight image prep (all 4 tensors in one kernel) ----------------
__global__ void prep_w_all(const float* __restrict__ W_up, const float* __restrict__ W1,
                           const float* __restrict__ W2a, const float* __restrict__ W2b,
                           __half* __restrict__ Wup, __half* __restrict__ W1r,
                           __half* __restrict__ W2ar, __half* __restrict__ W2br)
{
    int i = blockIdx.x * blockDim.x + threadIdx.x;   // < 180*8192
    int s = i >> 13;
    int within = i & 8191;
    const float* W; __half* O; int C;
    if (s < 20)       { W = W_up; O = Wup;  C = 128; }
    else if (s < 100) { W = W1;   O = W1r;  C = 512; s -= 20; }
    else if (s < 140) { W = W2a;  O = W2ar; C = 256; s -= 100; }
    else              { W = W2b;  O = W2br; C = 256; s -= 140; }
    int o = within >> 5;
    int k = within & 31;
    int cc = s / 5, r = s % 5;
    int kind, c;
    if (r == 0) {
        kind = 0; c = 32 * cc + k;
    } else {
        int base  = (r <= 2) ? 1 : 2;
        int pairc = 32 * cc + ((r == 2 || r == 4) ? 16 : 0);
        if (k < 16) { kind = base;     c = pairc + k; }
        else        { kind = base + 2; c = pairc + k - 16; }
    }
    O[(size_t)s * 8192 + within] = __float2half_rn(W[(o * C + c) * 5 + kind]);
}

// ---------------- merged transpose: from_up -> U, from_down -> X cols 256.. ----------------
__global__ void trans_both(const float* __restrict__ from_up, const float* __restrict__ from_down,
                           float* __restrict__ U, float* __restrict__ X)
{
    __shared__ float tile[32][33];
    int b  = blockIdx.z;
    int e0 = blockIdx.x * 32;
    const float* in; float* out; int C, os, coff, c0;
    if (blockIdx.y < 4) { in = from_up;   out = U; C = 128; os = 128; coff = 0;   c0 = blockIdx.y * 32; }
    else                { in = from_down; out = X; C = 256; os = 512; coff = 256; c0 = (blockIdx.y - 4) * 32; }
    const float* ip = in + ((size_t)b * C + c0) * E_ + e0;
    #pragma unroll
    for (int i = threadIdx.y; i < 32; i += 8)
        tile[i][threadIdx.x] = ip[(size_t)i * E_ + threadIdx.x];
    __syncthreads();
    float* op = out + ((size_t)(b * E_ + e0)) * os + coff + c0;
    #pragma unroll
    for (int i = threadIdx.y; i < 32; i += 8)
        op[(size_t)i * os + threadIdx.x] = tile[threadIdx.x][i];
}

// ---------------- fused gather + fp16 tensor-core GEMM (+ stats, + input-norm) ----------------
// 128 edges x 256 outs, 512 threads (16 warps 4x4, warp tile 32x64).
// 2 slabs per __syncthreads: A = 4 linear slab buffers (slab -> buf s&3);
// B = 6 slab buffers as 3-stage ring of 2-slab groups (stage (s>>1)%3), cp.async
// prefetch distance 1 iteration, wait_group 1. Gathers/stores interleave with MMAs.
#define ALD 40                         // row stride in halves (80 B, 16B-aligned rows)
#define A_HALFS (128 * ALD)            // 5120
#define B_HALFS (256 * ALD)            // 10240
#define A_BYTES (A_HALFS * 2)          // 10240
#define B_BYTES (B_HALFS * 2)          // 20480
#define SMEM_BYTES (4 * A_BYTES + 6 * B_BYTES + 512 * 4)   // 165888

template <bool NORM>
__global__ __launch_bounds__(512)
void gconv_mma(const float* __restrict__ Xin, int C,
               const int* __restrict__ ei,
               const __half* __restrict__ Wimg,
               const float* __restrict__ bias,
               float* __restrict__ Yout, int ys,
               float* __restrict__ gsum, float* __restrict__ gssq,
               const float* __restrict__ nmean, const float* __restrict__ nrstd,
               float* __restrict__ zbuf)
{
    extern __shared__ __half smh[];
    __half* smA = smh;                          // 4 slab buffers
    __half* smB = smh + 4 * A_HALFS;            // 6 slab buffers
    int*    aux_i = (int*)(smh + 4 * A_HALFS + 6 * B_HALFS);   // 512 ints
    float*  aux_f = (float*)aux_i;              // reused: [0..255]=mean, [256..511]=rstd
    const uint32_t sA_u32 = smem_u32(smA);
    const uint32_t sB_u32 = smem_u32(smB);

    const int tid  = threadIdx.x;
    const int wid  = tid >> 5;
    const int lane = tid & 31;
    const int g = lane >> 2;
    const int t = lane & 3;
    const int wm = wid >> 2;     // 0..3: 32-edge quarter
    const int wn = wid & 3;      // 0..3: 64-out quarter
    const int b  = blockIdx.z;
    const int e0 = blockIdx.x * 128;

    // one-time zero of the stats array (conv1 only)
    if (zbuf && b == 0 && blockIdx.x < 6) {
        float* zp = zbuf + blockIdx.x * 2048;
        *(float4*)&zp[tid * 4] = make_float4(0.f, 0.f, 0.f, 0.f);
    }

    {
        const int* eip = ei + ((size_t)(b * E_) + e0) * 4;
        aux_i[tid] = (b * E_ + eip[tid]) * C;
    }
    __syncthreads();
    const int nb0 = aux_i[(tid >> 2) * 4 + 0];
    const int nb1 = aux_i[(tid >> 2) * 4 + 1];
    const int nb2 = aux_i[(tid >> 2) * 4 + 2];
    const int nb3 = aux_i[(tid >> 2) * 4 + 3];
    if (NORM) {
        __syncthreads();
        aux_f[tid] = (tid < 256) ? nmean[b * 256 + tid]
                                 : nrstd[b * 256 + (tid - 256)];
    }
    __syncthreads();

    const int x0base = (b * E_ + e0) * C;
    const int slabs  = 5 * (C / 32);
    const int niter  = slabs >> 1;     // slabs always even

    float acc[2][8][4];
    #pragma unroll
    for (int mt = 0; mt < 2; mt++)
        #pragma unroll
        for (int nt = 0; nt < 8; nt++)
            #pragma unroll
            for (int rr = 0; rr < 4; rr++) acc[mt][nt][rr] = 0.f;

    float4 ga[2];

    auto norm4 = [&](float4 v, int cb) -> float4 {
        float4 m4 = *(float4*)&aux_f[cb];
        float4 r4 = *(float4*)&aux_f[256 + cb];
        v.x = fmaxf((v.x - m4.x) * r4.x, 0.f);
        v.y = fmaxf((v.y - m4.y) * r4.y, 0.f);
        v.z = fmaxf((v.z - m4.z) * r4.z, 0.f);
        v.w = fmaxf((v.w - m4.w) * r4.w, 0.f);
        return v;
    };

    auto gather = [&](int s) {
        int cc = s / 5, r = s % 5;
        if (r == 0) {
            int cbn = 32 * cc + (tid & 7) * 4;
            #pragma unroll
            for (int j = 0; j < 2; j++) {
                int v = tid + j * 512;
                int edge = v >> 3, c4 = (v & 7) * 4;
                ga[j] = *(const float4*)&Xin[x0base + edge * C + 32 * cc + c4];
                if (NORM) ga[j] = norm4(ga[j], cbn);
            }
        } else {
            int na = (r <= 2) ? 0 : 1;
            int pc = 32 * cc + ((r == 2 || r == 4) ? 16 : 0);
            int c4 = (tid & 3) * 4;
            int c = pc + c4;
            int basep = (na == 0) ? nb0 : nb1;
            int baseq = (na == 0) ? nb2 : nb3;
            float4 p = *(const float4*)&Xin[basep + c];
            float4 q = *(const float4*)&Xin[baseq + c];
            if (NORM) { p = norm4(p, c); q = norm4(q, c); }
            ga[0] = make_float4(p.x + q.x, p.y + q.y, p.z + q.z, p.w + q.w);
            ga[1] = make_float4(fabsf(p.x - q.x), fabsf(p.y - q.y),
                                fabsf(p.z - q.z), fabsf(p.w - q.w));
        }
    };
    auto storeA = [&](int s) {
        __half* A = smA + (s & 3) * A_HALFS;
        int r = s % 5;
        if (r == 0) {
            #pragma unroll
            for (int j = 0; j < 2; j++) {
                int v = tid + j * 512;
                int edge = v >> 3, k = (v & 7) * 4;
                float4 a = ga[j];
                *(uint2*)&A[edge * ALD + k] = make_uint2(h2u(a.x, a.y), h2u(a.z, a.w));
            }
        } else {
            int edge = tid >> 2, k = (tid & 3) * 4;
            float4 sv = ga[0], dv = ga[1];
            *(uint2*)&A[edge * ALD + k]      = make_uint2(h2u(sv.x, sv.y), h2u(sv.z, sv.w));
            *(uint2*)&A[edge * ALD + 16 + k] = make_uint2(h2u(dv.x, dv.y), h2u(dv.z, dv.w));
        }
    };
    auto copyB = [&](int s, int bufidx) {
        const __half* src = Wimg + (size_t)s * 8192;
        uint32_t dstb = sB_u32 + (uint32_t)bufidx * B_BYTES;
        #pragma unroll
        for (int j = 0; j < 2; j++) {
            int idx = tid + j * 512;
            int o = idx >> 2, seg = (idx & 3) * 8;   // halves
            CP_ASYNC16(dstb + (uint32_t)(o * ALD + seg) * 2, src + o * 32 + seg);
        }
    };
    auto mma_slab = [&](int slab, int bbuf) {
        const uint32_t Abase = sA_u32 + (uint32_t)(slab & 3) * A_BYTES;
        const uint32_t Bbase = sB_u32 + (uint32_t)bbuf * B_BYTES;
        #pragma unroll
        for (int ks = 0; ks < 2; ks++) {
            uint32_t af[2][4], bf[8][2];
            #pragma unroll
            for (int mt = 0; mt < 2; mt++) {
                int row = wm * 32 + mt * 16 + (lane & 15);
                int kof = ks * 16 + ((lane & 16) ? 8 : 0);
                LDSM_X4(af[mt][0], af[mt][1], af[mt][2], af[mt][3],
                        Abase + (uint32_t)(row * ALD + kof) * 2);
            }
            #pragma unroll
            for (int np = 0; np < 4; np++) {
                int nrow = wn * 64 + np * 16 + (lane & 7) + ((lane & 16) ? 8 : 0);
                int kof  = ks * 16 + ((lane & 8) ? 8 : 0);
                LDSM_X4(bf[2 * np][0], bf[2 * np][1], bf[2 * np + 1][0], bf[2 * np + 1][1],
                        Bbase + (uint32_t)(nrow * ALD + kof) * 2);
            }
            #pragma unroll
            for (int mt = 0; mt < 2; mt++)
                #pragma unroll
                for (int nt = 0; nt < 8; nt++)
                    mma16816(acc[mt][nt], af[mt], bf[nt]);
        }
    };

    // prologue: B stage 0 (slabs 0,1); A slabs 0,1
    copyB(0, 0);
    copyB(1, 1);
    CP_COMMIT();
    gather(0); storeA(0);
    gather(1); storeA(1);

    for (int i = 0; i < niter; i++) {
        int s0 = 2 * i;
        bool more = (i + 1 < niter);
        if (more) {
            int st = ((i + 1) % 3) * 2;
            copyB(s0 + 2, st);
            copyB(s0 + 3, st + 1);
        }
        CP_COMMIT();                    // constant group cadence
        if (more) gather(s0 + 2);       // LDGs in flight across wait+sync
        CP_WAIT1();                     // stage i%3 complete
        __syncthreads();

        int bb = (i % 3) * 2;
        mma_slab(s0, bb);
        if (more) { storeA(s0 + 2); gather(s0 + 3); }
        mma_slab(s0 + 1, bb + 1);
        if (more) storeA(s0 + 3);
    }

    // ---- epilogue: +bias, float2 stores, optional per-channel stats ----
    #pragma unroll
    for (int nt = 0; nt < 8; nt++) {
        int col = wn * 64 + nt * 8 + 2 * t;
        float bv0 = bias[col], bv1 = bias[col + 1];
        float s0 = 0.f, q0 = 0.f, s1 = 0.f, q1 = 0.f;
        #pragma unroll
        for (int mt = 0; mt < 2; mt++) {
            int row = e0 + wm * 32 + mt * 16 + g;
            float a0 = acc[mt][nt][0] + bv0, a1 = acc[mt][nt][1] + bv1;
            float a2 = acc[mt][nt][2] + bv0, a3 = acc[mt][nt][3] + bv1;
            *(float2*)&Yout[((size_t)(b * E_ + row)) * ys + col] = make_float2(a0, a1);
            *(float2*)&Yout[((size_t)(b * E_ + row + 8)) * ys + col] = make_float2(a2, a3);
            s0 += a0 + a2;  q0 += a0 * a0 + a2 * a2;
            s1 += a1 + a3;  q1 += a1 * a1 + a3 * a3;
        }
        if (gsum) {
            #pragma unroll
            for (int m = 16; m >= 4; m >>= 1) {
                s0 += __shfl_xor_sync(0xffffffffu, s0, m);
                q0 += __shfl_xor_sync(0xffffffffu, q0, m);
                s1 += __shfl_xor_sync(0xffffffffu, s1, m);
                q1 += __shfl_xor_sync(0xffffffffu, q1, m);
            }
            if (g == 0) {
                atomicAdd(&gsum[b * 256 + col],     s0);
                atomicAdd(&gsum[b * 256 + col + 1], s1);
                atomicAdd(&gssq[b * 256 + col],     q0);
                atomicAdd(&gssq[b * 256 + col + 1], q1);
            }
        }
    }
}

// ---------------- finalize stats ----------------
__global__ void finalize_stats(const float* __restrict__ gsum, const float* __restrict__ gssq,
                               float* __restrict__ mean, float* __restrict__ rstd)
{
    int i = blockIdx.x * blockDim.x + threadIdx.x;
    if (i < B_ * 256) {
        float m = gsum[i] * (1.f / E_);
        float v = gssq[i] * (1.f / E_) - m * m;
        mean[i] = m;
        rstd[i] = rsqrtf(v + 1e-5f);
    }
}

// block-A combine: X2 = relu((Z2-m2)*r2 + relu((Z1-m1)*r1))
__global__ void apply_norm2(const float* __restrict__ Z2, const float* __restrict__ Z1,
                            const float* __restrict__ mean2, const float* __restrict__ rstd2,
                            const float* __restrict__ mean1, const float* __restrict__ rstd1,
                            float* __restrict__ out)
{
    size_t i = (size_t)blockIdx.x * blockDim.x + threadIdx.x;   // float4 index
    int b = (int)(i >> 20);
    int c = ((int)i & 63) * 4;
    float4 z2 = ((const float4*)Z2)[i];
    float4 z1 = ((const float4*)Z1)[i];
    int mi = b * 256 + c;
    float4 o;
    {
        float x1x = fmaxf((z1.x - mean1[mi])     * rstd1[mi],     0.f);
        float x1y = fmaxf((z1.y - mean1[mi + 1]) * rstd1[mi + 1], 0.f);
        float x1z = fmaxf((z1.z - mean1[mi + 2]) * rstd1[mi + 2], 0.f);
        float x1w = fmaxf((z1.w - mean1[mi + 3]) * rstd1[mi + 3], 0.f);
        o.x = fmaxf((z2.x - mean2[mi])     * rstd2[mi]     + x1x, 0.f);
        o.y = fmaxf((z2.y - mean2[mi + 1]) * rstd2[mi + 1] + x1y, 0.f);
        o.z = fmaxf((z2.z - mean2[mi + 2]) * rstd2[mi + 2] + x1z, 0.f);
        o.w = fmaxf((z2.w - mean2[mi + 3]) * rstd2[mi + 3] + x1w, 0.f);
    }
    ((float4*)out)[i] = o;
}

// final: relu((Z-mean)*rstd + res) with transposed store -> [B,256,E]
__global__ void apply_norm_t(const float* __restrict__ Z, const float* __restrict__ res,
                             const float* __restrict__ mean, const float* __restrict__ rstd,
                             float* __restrict__ out)
{
    __shared__ float tile[32][33];
    int b  = blockIdx.z;
    int e0 = blockIdx.x * 32, c0 = blockIdx.y * 32;
    int c  = c0 + threadIdx.x;
    float m = mean[b * 256 + c], r = rstd[b * 256 + c];
    #pragma unroll
    for (int i = threadIdx.y; i < 32; i += 8) {
        size_t idx = ((size_t)(b * E_ + e0 + i)) * 256 + c;
        float v = (Z[idx] - m) * r + res[idx];
        tile[i][threadIdx.x] = fmaxf(v, 0.f);
    }
    __syncthreads();
    float* op = out + ((size_t)(b * 256 + c0)) * E_ + e0;
    #pragma unroll
    for (int i = threadIdx.y; i < 32; i += 8)
        op[(size_t)i * E_ + threadIdx.x] = tile[threadIdx.x][i];
}

// ---------------- host ----------------
extern "C" void kernel_launch(void* const* d_in, const int* in_sizes, int n_in,
                              void* d_out, int out_size)
{
    const float* from_up   = (const float*)d_in[0];
    const float* from_down = (const float*)d_in[1];
    const int*   ei        = (const int*)  d_in[2];
    const float* W_up = (const float*)d_in[3];
    const float* b_up = (const float*)d_in[4];
    const float* W1   = (const float*)d_in[5];
    const float* b1   = (const float*)d_in[6];
    const float* W2a  = (const float*)d_in[7];
    const float* b2a  = (const float*)d_in[8];
    const float* W2b  = (const float*)d_in[9];
    const float* b2b  = (const float*)d_in[10];
    float* out = (float*)d_out;

    float *U, *X, *Z, *Z2, *X2, *stats, *mean1, *rstd1, *mean2, *rstd2;
    __half *Wup, *W1r, *W2ar, *W2br;
    cudaGetSymbolAddress((void**)&U,    g_U);
    cudaGetSymbolAddress((void**)&X,    g_X);
    cudaGetSymbolAddress((void**)&Z,    g_Z);
    cudaGetSymbolAddress((void**)&Z2,   g_Z2);
    cudaGetSymbolAddress((void**)&X2,   g_X2);
    cudaGetSymbolAddress((void**)&Wup,  g_Wup);
    cudaGetSymbolAddress((void**)&W1r,  g_W1r);
    cudaGetSymbolAddress((void**)&W2ar, g_W2ar);
    cudaGetSymbolAddress((void**)&W2br, g_W2br);
    cudaGetSymbolAddress((void**)&stats, g_stats);
    cudaGetSymbolAddress((void**)&mean1, g_mean);
    cudaGetSymbolAddress((void**)&rstd1, g_rstd);
    cudaGetSymbolAddress((void**)&mean2, g_mean2);
    cudaGetSymbolAddress((void**)&rstd2, g_rstd2);

    float* sum1 = stats;           float* ssq1 = stats + 2048;
    float* sum2 = stats + 4096;    float* ssq2 = stats + 6144;
    float* sum3 = stats + 8192;    float* ssq3 = stats + 10240;

    cudaFuncSetAttribute(gconv_mma<false>, cudaFuncAttributeMaxDynamicSharedMemorySize, SMEM_BYTES);
    cudaFuncSetAttribute(gconv_mma<true>,  cudaFuncAttributeMaxDynamicSharedMemorySize, SMEM_BYTES);

    // (1) merged weight-image prep
    prep_w_all<<<(180 * 8192) / 256, 256>>>(W_up, W1, W2a, W2b, Wup, W1r, W2ar, W2br);

    // (2) merged input transposes
    trans_both<<<dim3(E_ / 32, 12, B_), dim3(32, 8)>>>(from_up, from_down, U, X);

    dim3 cg(E_ / 128, 1, B_);
    // (3) conv1 -> X cols 0..255; also zeroes the whole stats array
    gconv_mma<false><<<cg, 512, SMEM_BYTES>>>(U, 128, ei, Wup, b_up, X, 512,
                                              nullptr, nullptr, nullptr, nullptr, stats);

    // (4) conv2 -> Z1, fused stats  [ncu capture slot target]
    gconv_mma<false><<<cg, 512, SMEM_BYTES>>>(X, 512, ei, W1r, b1, Z, 256,
                                              sum1, ssq1, nullptr, nullptr, nullptr);
    finalize_stats<<<(B_ * 256 + 255) / 256, 256>>>(sum1, ssq1, mean1, rstd1);

    // conv3: gathers relu(norm1(Z1)) on the fly -> Z2, fused stats
    gconv_mma<true><<<cg, 512, SMEM_BYTES>>>(Z, 256, ei, W2ar, b2a, Z2, 256,
                                             sum2, ssq2, mean1, rstd1, nullptr);
    finalize_stats<<<(B_ * 256 + 255) / 256, 256>>>(sum2, ssq2, mean2, rstd2);

    // block-A combine: X2 = relu(norm2(Z2) + relu(norm1(Z1)))
    apply_norm2<<<32768, 256>>>(Z2, Z, mean2, rstd2, mean1, rstd1, X2);

    // conv4: X2 -> Z3 (reuse g_Z), fused stats
    gconv_mma<false><<<cg, 512, SMEM_BYTES>>>(X2, 256, ei, W2br, b2b, Z, 256,
                                              sum3, ssq3, nullptr, nullptr, nullptr);
    finalize_stats<<<(B_ * 256 + 255) / 256, 256>>>(sum3, ssq3, mean1, rstd1);

    // final: relu(norm(Z3) + X2), transposed straight to out
    apply_norm_t<<<dim3(E_ / 32, 256 / 32, B_), dim3(32, 8)>>>(Z, X2, mean1, rstd1, out);
}

// round 12
// speedup vs baseline: 4.9512x; 1.0484x over previous
#include <cuda_runtime.h>
#include <cuda_fp16.h>
#include <cuda_bf16.h>
#include <math.h>
#include <stdint.h>

#define B_ 8
#define E_ 16384
#define O_ 256

// ---------------- scratch (__device__ globals; no allocs allowed) ----------------
__device__ float g_U [(size_t)B_*E_*128];   // from_up, edge-major
__device__ float g_X [(size_t)B_*E_*512];   // concat(conv1, from_down), edge-major
__device__ float g_Z [(size_t)B_*E_*256];   // Z1 (conv2 out), later Z3 (conv4 out)
__device__ float g_Z2[(size_t)B_*E_*256];   // Z2 (conv3 out)
__device__ float g_X2[(size_t)B_*E_*256];   // block-A output (residual input for final)
__device__ __half g_Wup [5*128*256];
__device__ __half g_W1r [5*512*256];
__device__ __half g_W2ar[5*256*256];
__device__ __half g_W2br[5*256*256];
// stats: [0]=sum1 [2048]=ssq1 [4096]=sum2 [6144]=ssq2 [8192]=sum3 [10240]=ssq3
__device__ float g_stats[6*2048];
__device__ float g_mean [B_*256];
__device__ float g_rstd [B_*256];
__device__ float g_mean2[B_*256];
__device__ float g_rstd2[B_*256];

__device__ __forceinline__ uint32_t smem_u32(const void* p) {
    uint32_t a;
    asm("{ .reg .u64 t; cvta.to.shared.u64 t, %1; cvt.u32.u64 %0, t; }" : "=r"(a) : "l"(p));
    return a;
}
#define CP_ASYNC16(dst, src) \
    asm volatile("cp.async.cg.shared.global [%0], [%1], 16;" :: "r"(dst), "l"(src))
#define CP_COMMIT() asm volatile("cp.async.commit_group;" ::: "memory")
#define CP_WAIT2()  asm volatile("cp.async.wait_group 2;" ::: "memory")
#define CP_WAIT0()  asm volatile("cp.async.wait_group 0;" ::: "memory")
#define BAR_SYNC_N(id, cnt)   asm volatile("bar.sync %0, %1;"   :: "r"(id), "r"(cnt) : "memory")
#define BAR_ARRIVE_N(id, cnt) asm volatile("bar.arrive %0, %1;" :: "r"(id), "r"(cnt) : "memory")
#define LDSM_X4(r0, r1, r2, r3, addr) \
    asm volatile("ldmatrix.sync.aligned.m8n8.x4.shared.b16 {%0,%1,%2,%3}, [%4];" \
        : "=r"(r0), "=r"(r1), "=r"(r2), "=r"(r3) : "r"(addr))

__device__ __forceinline__ void mma16816(float* d, const uint32_t* a, const uint32_t* b)
{
    asm volatile(
        "mma.sync.aligned.m16n8k16.row.col.f32.f16.f16.f32 "
        "{%0,%1,%2,%3}, {%4,%5,%6,%7}, {%8,%9}, {%0,%1,%2,%3};"
        : "+f"(d[0]), "+f"(d[1]), "+f"(d[2]), "+f"(d[3])
        : "r"(a[0]), "r"(a[1]), "r"(a[2]), "r"(a[3]), "r"(b[0]), "r"(b[1]));
}

__device__ __forceinline__ uint32_t h2u(float x, float y) {
    __half2 h = __floats2half2_rn(x, y);
    return *reinterpret_cast<uint32_t*>(&h);
}

// ---------------- slab map ----------------
// slab s (32 K-rows): cc = s/5, r = s%5
//  r=0: kind0 (center), channels [32cc, +32)
//  r=1: pair(1,3) chunk [32cc, +16)      rows 0-15 = n1+n3, rows 16-31 = |n1-n3|
//  r=2: pair(1,3) chunk [32cc+16, +16)
//  r=3: pair(2,4) chunk [32cc, +16)
//  r=4: pair(2,4) chunk [32cc+16, +16)

// ---------------- merged weight image prep ----------------
__global__ void prep_w_all(const float* __restrict__ W_up, const float* __restrict__ W1,
                           const float* __restrict__ W2a, const float* __restrict__ W2b,
                           __half* __restrict__ Wup, __half* __restrict__ W1r,
                           __half* __restrict__ W2ar, __half* __restrict__ W2br)
{
    int i = blockIdx.x * blockDim.x + threadIdx.x;   // < 180*8192
    int s = i >> 13;
    int within = i & 8191;
    const float* W; __half* O; int C;
    if (s < 20)       { W = W_up; O = Wup;  C = 128; }
    else if (s < 100) { W = W1;   O = W1r;  C = 512; s -= 20; }
    else if (s < 140) { W = W2a;  O = W2ar; C = 256; s -= 100; }
    else              { W = W2b;  O = W2br; C = 256; s -= 140; }
    int o = within >> 5;
    int k = within & 31;
    int cc = s / 5, r = s % 5;
    int kind, c;
    if (r == 0) {
        kind = 0; c = 32 * cc + k;
    } else {
        int base  = (r <= 2) ? 1 : 2;
        int pairc = 32 * cc + ((r == 2 || r == 4) ? 16 : 0);
        if (k < 16) { kind = base;     c = pairc + k; }
        else        { kind = base + 2; c = pairc + k - 16; }
    }
    O[(size_t)s * 8192 + within] = __float2half_rn(W[(o * C + c) * 5 + kind]);
}

// ---------------- merged transpose ----------------
__global__ void trans_both(const float* __restrict__ from_up, const float* __restrict__ from_down,
                           float* __restrict__ U, float* __restrict__ X)
{
    __shared__ float tile[32][33];
    int b  = blockIdx.z;
    int e0 = blockIdx.x * 32;
    const float* in; float* out; int C, os, coff, c0;
    if (blockIdx.y < 4) { in = from_up;   out = U; C = 128; os = 128; coff = 0;   c0 = blockIdx.y * 32; }
    else                { in = from_down; out = X; C = 256; os = 512; coff = 256; c0 = (blockIdx.y - 4) * 32; }
    const float* ip = in + ((size_t)b * C + c0) * E_ + e0;
    #pragma unroll
    for (int i = threadIdx.y; i < 32; i += 8)
        tile[i][threadIdx.x] = ip[(size_t)i * E_ + threadIdx.x];
    __syncthreads();
    float* op = out + ((size_t)(b * E_ + e0)) * os + coff + c0;
    #pragma unroll
    for (int i = threadIdx.y; i < 32; i += 8)
        op[(size_t)i * os + threadIdx.x] = tile[threadIdx.x][i];
}

// ---------------- warp-specialized fused gather + fp16 MMA ----------------
// 384 threads: warps 0-7 = consumers (2x4 grid, 64x64 warp tile, pure LDSM+MMA);
// warps 8-11 = producers (gather + STS A + cp.async B).
// 4-stage A/B rings. Named barriers: produce-done[st]=1+st, consume-done[st]=5+st,
// count 384 (producers 128 + consumers 256). Producer signals slab s-2 after
// cp.async.wait_group 2; waits consume-done before overwriting a stage.
#define ALD 40                         // row stride in halves
#define A_HALFS (128 * ALD)            // 5120
#define B_HALFS (256 * ALD)            // 10240
#define A_BYTES (A_HALFS * 2)          // 10240
#define B_BYTES (B_HALFS * 2)          // 20480
#define WS_SMEM (4 * A_BYTES + 4 * B_BYTES + 512 * 4 + 512 * 4)   // 126976

template <bool NORM>
__global__ __launch_bounds__(384)
void gconv_ws(const float* __restrict__ Xin, int C,
              const int* __restrict__ ei,
              const __half* __restrict__ Wimg,
              const float* __restrict__ bias,
              float* __restrict__ Yout, int ys,
              float* __restrict__ gsum, float* __restrict__ gssq,
              const float* __restrict__ nmean, const float* __restrict__ nrstd,
              float* __restrict__ zbuf)
{
    extern __shared__ __half smh[];
    __half* smA = smh;                          // 4 stages
    __half* smB = smh + 4 * A_HALFS;            // 4 stages
    int*    snb = (int*)(smh + 4 * A_HALFS + 4 * B_HALFS);   // 512 ints
    float*  nrm = (float*)(snb + 512);                       // 512 floats
    const uint32_t sA_u32 = smem_u32(smA);
    const uint32_t sB_u32 = smem_u32(smB);

    const int tid  = threadIdx.x;
    const int wid  = tid >> 5;
    const int lane = tid & 31;
    const int b  = blockIdx.z;
    const int e0 = blockIdx.x * 128;

    // one-time zero of stats (conv1 only): blocks 0..7 x 1536 floats
    if (zbuf && b == 0 && blockIdx.x < 8)
        *(float4*)&zbuf[blockIdx.x * 1536 + tid * 4] = make_float4(0.f, 0.f, 0.f, 0.f);

    {
        const int* eip = ei + ((size_t)(b * E_) + e0) * 4;
        for (int i = tid; i < 512; i += 384)
            snb[i] = (b * E_ + eip[i]) * C;
    }
    if (NORM) {
        for (int i = tid; i < 512; i += 384)
            nrm[i] = (i < 256) ? nmean[b * 256 + i] : nrstd[b * 256 + (i - 256)];
    }
    __syncthreads();

    const int x0base = (b * E_ + e0) * C;
    const int slabs  = 5 * (C / 32);

    auto norm4 = [&](float4 v, int cb) -> float4 {
        float4 m4 = *(float4*)&nrm[cb];
        float4 r4 = *(float4*)&nrm[256 + cb];
        v.x = fmaxf((v.x - m4.x) * r4.x, 0.f);
        v.y = fmaxf((v.y - m4.y) * r4.y, 0.f);
        v.z = fmaxf((v.z - m4.z) * r4.z, 0.f);
        v.w = fmaxf((v.w - m4.w) * r4.w, 0.f);
        return v;
    };

    if (wid >= 8) {
        // =================== producers (128 threads) ===================
        const int tp = tid - 256;
        for (int s = 0; s < slabs; s++) {
            int st = s & 3;
            if (s >= 4) BAR_SYNC_N(5 + st, 384);     // stage free?
            // B copy (cp.async)
            {
                const __half* src = Wimg + (size_t)s * 8192;
                uint32_t dstb = sB_u32 + (uint32_t)st * B_BYTES;
                #pragma unroll
                for (int j = 0; j < 8; j++) {
                    int idx = tp + j * 128;
                    int o = idx >> 2, seg = (idx & 3) * 8;
                    CP_ASYNC16(dstb + (uint32_t)(o * ALD + seg) * 2, src + o * 32 + seg);
                }
                CP_COMMIT();
            }
            // A gather + STS
            {
                int cc = s / 5, r = s % 5;
                __half* A = smA + st * A_HALFS;
                if (r == 0) {
                    float4 v[8];
                    #pragma unroll
                    for (int j = 0; j < 8; j++) {
                        int vi = tp + j * 128;
                        int edge = vi >> 3, c4 = (vi & 7) * 4;
                        v[j] = *(const float4*)&Xin[x0base + edge * C + 32 * cc + c4];
                    }
                    #pragma unroll
                    for (int j = 0; j < 8; j++) {
                        int vi = tp + j * 128;
                        int edge = vi >> 3, k = (vi & 7) * 4;
                        float4 a = NORM ? norm4(v[j], 32 * cc + k) : v[j];
                        *(uint2*)&A[edge * ALD + k] = make_uint2(h2u(a.x, a.y), h2u(a.z, a.w));
                    }
                } else {
                    int na = (r <= 2) ? 0 : 1;
                    int pc = 32 * cc + ((r == 2 || r == 4) ? 16 : 0);
                    float4 p[4], q[4];
                    #pragma unroll
                    for (int j = 0; j < 4; j++) {
                        int vi = tp + j * 128;
                        int edge = vi >> 2, c4 = (vi & 3) * 4;
                        int c = pc + c4;
                        p[j] = *(const float4*)&Xin[snb[edge * 4 + na] + c];
                        q[j] = *(const float4*)&Xin[snb[edge * 4 + na + 2] + c];
                    }
                    #pragma unroll
                    for (int j = 0; j < 4; j++) {
                        int vi = tp + j * 128;
                        int edge = vi >> 2, k = (vi & 3) * 4;
                        float4 pp = p[j], qq = q[j];
                        if (NORM) { pp = norm4(pp, pc + k); qq = norm4(qq, pc + k); }
                        float4 sv = make_float4(pp.x + qq.x, pp.y + qq.y, pp.z + qq.z, pp.w + qq.w);
                        float4 dv = make_float4(fabsf(pp.x - qq.x), fabsf(pp.y - qq.y),
                                                fabsf(pp.z - qq.z), fabsf(pp.w - qq.w));
                        *(uint2*)&A[edge * ALD + k]      = make_uint2(h2u(sv.x, sv.y), h2u(sv.z, sv.w));
                        *(uint2*)&A[edge * ALD + 16 + k] = make_uint2(h2u(dv.x, dv.y), h2u(dv.z, dv.w));
                    }
                }
            }
            if (s >= 2) {
                CP_WAIT2();                              // groups <= s-2 retired
                BAR_ARRIVE_N(1 + ((s - 2) & 3), 384);    // slab s-2 ready
            }
        }
        CP_WAIT0();
        BAR_ARRIVE_N(1 + ((slabs - 2) & 3), 384);
        BAR_ARRIVE_N(1 + ((slabs - 1) & 3), 384);
    } else {
        // =================== consumers (8 warps, 64x64 tiles) ===================
        const int g = lane >> 2;
        const int t = lane & 3;
        const int wm = wid >> 2;     // 0..1: 64-edge half
        const int wn = wid & 3;      // 0..3: 64-out quarter

        float acc[4][8][4];
        #pragma unroll
        for (int mt = 0; mt < 4; mt++)
            #pragma unroll
            for (int nt = 0; nt < 8; nt++)
                #pragma unroll
                for (int rr = 0; rr < 4; rr++) acc[mt][nt][rr] = 0.f;

        for (int s = 0; s < slabs; s++) {
            int st = s & 3;
            BAR_SYNC_N(1 + st, 384);                 // slab ready
            const uint32_t Abase = sA_u32 + (uint32_t)st * A_BYTES;
            const uint32_t Bbase = sB_u32 + (uint32_t)st * B_BYTES;
            #pragma unroll
            for (int ks = 0; ks < 2; ks++) {
                uint32_t af[4][4];
                #pragma unroll
                for (int mt = 0; mt < 4; mt++) {
                    int row = wm * 64 + mt * 16 + (lane & 15);
                    int kof = ks * 16 + ((lane & 16) ? 8 : 0);
                    LDSM_X4(af[mt][0], af[mt][1], af[mt][2], af[mt][3],
                            Abase + (uint32_t)(row * ALD + kof) * 2);
                }
                #pragma unroll
                for (int np = 0; np < 4; np++) {
                    uint32_t b0, b1, b2, b3;
                    int nrow = wn * 64 + np * 16 + (lane & 7) + ((lane & 16) ? 8 : 0);
                    int kof  = ks * 16 + ((lane & 8) ? 8 : 0);
                    LDSM_X4(b0, b1, b2, b3, Bbase + (uint32_t)(nrow * ALD + kof) * 2);
                    uint32_t bf0[2] = {b0, b1}, bf1[2] = {b2, b3};
                    #pragma unroll
                    for (int mt = 0; mt < 4; mt++) {
                        mma16816(acc[mt][2 * np],     af[mt], bf0);
                        mma16816(acc[mt][2 * np + 1], af[mt], bf1);
                    }
                }
            }
            BAR_ARRIVE_N(5 + st, 384);               // stage free
        }

        // ---- epilogue: +bias, float2 stores, optional stats ----
        #pragma unroll
        for (int nt = 0; nt < 8; nt++) {
            int col = wn * 64 + nt * 8 + 2 * t;
            float bv0 = bias[col], bv1 = bias[col + 1];
            float s0 = 0.f, q0 = 0.f, s1 = 0.f, q1 = 0.f;
            #pragma unroll
            for (int mt = 0; mt < 4; mt++) {
                int row = e0 + wm * 64 + mt * 16 + g;
                float a0 = acc[mt][nt][0] + bv0, a1 = acc[mt][nt][1] + bv1;
                float a2 = acc[mt][nt][2] + bv0, a3 = acc[mt][nt][3] + bv1;
                *(float2*)&Yout[((size_t)(b * E_ + row)) * ys + col] = make_float2(a0, a1);
                *(float2*)&Yout[((size_t)(b * E_ + row + 8)) * ys + col] = make_float2(a2, a3);
                s0 += a0 + a2;  q0 += a0 * a0 + a2 * a2;
                s1 += a1 + a3;  q1 += a1 * a1 + a3 * a3;
            }
            if (gsum) {
                #pragma unroll
                for (int m = 16; m >= 4; m >>= 1) {
                    s0 += __shfl_xor_sync(0xffffffffu, s0, m);
                    q0 += __shfl_xor_sync(0xffffffffu, q0, m);
                    s1 += __shfl_xor_sync(0xffffffffu, s1, m);
                    q1 += __shfl_xor_sync(0xffffffffu, q1, m);
                }
                if (g == 0) {
                    atomicAdd(&gsum[b * 256 + col],     s0);
                    atomicAdd(&gsum[b * 256 + col + 1], s1);
                    atomicAdd(&gssq[b * 256 + col],     q0);
                    atomicAdd(&gssq[b * 256 + col + 1], q1);
                }
            }
        }
    }
}

// ---------------- finalize stats ----------------
__global__ void finalize_stats(const float* __restrict__ gsum, const float* __restrict__ gssq,
                               float* __restrict__ mean, float* __restrict__ rstd)
{
    int i = blockIdx.x * blockDim.x + threadIdx.x;
    if (i < B_ * 256) {
        float m = gsum[i] * (1.f / E_);
        float v = gssq[i] * (1.f / E_) - m * m;
        mean[i] = m;
        rstd[i] = rsqrtf(v + 1e-5f);
    }
}

// block-A combine: X2 = relu((Z2-m2)*r2 + relu((Z1-m1)*r1))
__global__ void apply_norm2(const float* __restrict__ Z2, const float* __restrict__ Z1,
                            const float* __restrict__ mean2, const float* __restrict__ rstd2,
                            const float* __restrict__ mean1, const float* __restrict__ rstd1,
                            float* __restrict__ out)
{
    size_t i = (size_t)blockIdx.x * blockDim.x + threadIdx.x;   // float4 index
    int b = (int)(i >> 20);
    int c = ((int)i & 63) * 4;
    float4 z2 = ((const float4*)Z2)[i];
    float4 z1 = ((const float4*)Z1)[i];
    int mi = b * 256 + c;
    float4 o;
    {
        float x1x = fmaxf((z1.x - mean1[mi])     * rstd1[mi],     0.f);
        float x1y = fmaxf((z1.y - mean1[mi + 1]) * rstd1[mi + 1], 0.f);
        float x1z = fmaxf((z1.z - mean1[mi + 2]) * rstd1[mi + 2], 0.f);
        float x1w = fmaxf((z1.w - mean1[mi + 3]) * rstd1[mi + 3], 0.f);
        o.x = fmaxf((z2.x - mean2[mi])     * rstd2[mi]     + x1x, 0.f);
        o.y = fmaxf((z2.y - mean2[mi + 1]) * rstd2[mi + 1] + x1y, 0.f);
        o.z = fmaxf((z2.z - mean2[mi + 2]) * rstd2[mi + 2] + x1z, 0.f);
        o.w = fmaxf((z2.w - mean2[mi + 3]) * rstd2[mi + 3] + x1w, 0.f);
    }
    ((float4*)out)[i] = o;
}

// final: relu((Z-mean)*rstd + res) with transposed store -> [B,256,E]
__global__ void apply_norm_t(const float* __restrict__ Z, const float* __restrict__ res,
                             const float* __restrict__ mean, const float* __restrict__ rstd,
                             float* __restrict__ out)
{
    __shared__ float tile[32][33];
    int b  = blockIdx.z;
    int e0 = blockIdx.x * 32, c0 = blockIdx.y * 32;
    int c  = c0 + threadIdx.x;
    float m = mean[b * 256 + c], r = rstd[b * 256 + c];
    #pragma unroll
    for (int i = threadIdx.y; i < 32; i += 8) {
        size_t idx = ((size_t)(b * E_ + e0 + i)) * 256 + c;
        float v = (Z[idx] - m) * r + res[idx];
        tile[i][threadIdx.x] = fmaxf(v, 0.f);
    }
    __syncthreads();
    float* op = out + ((size_t)(b * 256 + c0)) * E_ + e0;
    #pragma unroll
    for (int i = threadIdx.y; i < 32; i += 8)
        op[(size_t)i * E_ + threadIdx.x] = tile[threadIdx.x][i];
}

// ---------------- host ----------------
extern "C" void kernel_launch(void* const* d_in, const int* in_sizes, int n_in,
                              void* d_out, int out_size)
{
    const float* from_up   = (const float*)d_in[0];
    const float* from_down = (const float*)d_in[1];
    const int*   ei        = (const int*)  d_in[2];
    const float* W_up = (const float*)d_in[3];
    const float* b_up = (const float*)d_in[4];
    const float* W1   = (const float*)d_in[5];
    const float* b1   = (const float*)d_in[6];
    const float* W2a  = (const float*)d_in[7];
    const float* b2a  = (const float*)d_in[8];
    const float* W2b  = (const float*)d_in[9];
    const float* b2b  = (const float*)d_in[10];
    float* out = (float*)d_out;

    float *U, *X, *Z, *Z2, *X2, *stats, *mean1, *rstd1, *mean2, *rstd2;
    __half *Wup, *W1r, *W2ar, *W2br;
    cudaGetSymbolAddress((void**)&U,    g_U);
    cudaGetSymbolAddress((void**)&X,    g_X);
    cudaGetSymbolAddress((void**)&Z,    g_Z);
    cudaGetSymbolAddress((void**)&Z2,   g_Z2);
    cudaGetSymbolAddress((void**)&X2,   g_X2);
    cudaGetSymbolAddress((void**)&Wup,  g_Wup);
    cudaGetSymbolAddress((void**)&W1r,  g_W1r);
    cudaGetSymbolAddress((void**)&W2ar, g_W2ar);
    cudaGetSymbolAddress((void**)&W2br, g_W2br);
    cudaGetSymbolAddress((void**)&stats, g_stats);
    cudaGetSymbolAddress((void**)&mean1, g_mean);
    cudaGetSymbolAddress((void**)&rstd1, g_rstd);
    cudaGetSymbolAddress((void**)&mean2, g_mean2);
    cudaGetSymbolAddress((void**)&rstd2, g_rstd2);

    float* sum1 = stats;           float* ssq1 = stats + 2048;
    float* sum2 = stats + 4096;    float* ssq2 = stats + 6144;
    float* sum3 = stats + 8192;    float* ssq3 = stats + 10240;

    cudaFuncSetAttribute(gconv_ws<false>, cudaFuncAttributeMaxDynamicSharedMemorySize, WS_SMEM);
    cudaFuncSetAttribute(gconv_ws<true>,  cudaFuncAttributeMaxDynamicSharedMemorySize, WS_SMEM);

    // (1) merged weight-image prep
    prep_w_all<<<(180 * 8192) / 256, 256>>>(W_up, W1, W2a, W2b, Wup, W1r, W2ar, W2br);

    // (2) merged input transposes
    trans_both<<<dim3(E_ / 32, 12, B_), dim3(32, 8)>>>(from_up, from_down, U, X);

    dim3 cg(E_ / 128, 1, B_);
    // (3) conv1 -> X cols 0..255; zeroes stats
    gconv_ws<false><<<cg, 384, WS_SMEM>>>(U, 128, ei, Wup, b_up, X, 512,
                                          nullptr, nullptr, nullptr, nullptr, stats);

    // (4) conv2 -> Z1, fused stats  [ncu capture slot target]
    gconv_ws<false><<<cg, 384, WS_SMEM>>>(X, 512, ei, W1r, b1, Z, 256,
                                          sum1, ssq1, nullptr, nullptr, nullptr);
    finalize_stats<<<(B_ * 256 + 255) / 256, 256>>>(sum1, ssq1, mean1, rstd1);

    // conv3: gathers relu(norm1(Z1)) on the fly -> Z2, fused stats
    gconv_ws<true><<<cg, 384, WS_SMEM>>>(Z, 256, ei, W2ar, b2a, Z2, 256,
                                         sum2, ssq2, mean1, rstd1, nullptr);
    finalize_stats<<<(B_ * 256 + 255) / 256, 256>>>(sum2, ssq2, mean2, rstd2);

    // block-A combine: X2 = relu(norm2(Z2) + relu(norm1(Z1)))
    apply_norm2<<<32768, 256>>>(Z2, Z, mean2, rstd2, mean1, rstd1, X2);

    // conv4: X2 -> Z3 (reuse g_Z), fused stats
    gconv_ws<false><<<cg, 384, WS_SMEM>>>(X2, 256, ei, W2br, b2b, Z, 256,
                                          sum3, ssq3, nullptr, nullptr, nullptr);
    finalize_stats<<<(B_ * 256 + 255) / 256, 256>>>(sum3, ssq3, mean1, rstd1);

    // final: relu(norm(Z3) + X2), transposed straight to out
    apply_norm_t<<<dim3(E_ / 32, 256 / 32, B_), dim3(32, 8)>>>(Z, X2, mean1, rstd1, out);
}